// round 4
// baseline (speedup 1.0000x reference)
#include <cuda_runtime.h>
#include <math.h>

// ---------------- problem constants ----------------
#define BATCHN   4
#define SEQT     8192
#define NCH      7
#define NPATCH   1023               // (8192-16)/8+1
#define MTOK     (BATCHN*NPATCH)    // 4092
#define DIMV     512
#define HIDV     2048
#define NHEAD    8
#define HDIM     64
#define PINLEN   112                // PATCH_LEN*C = 16*7

// ---------------- device scratch (allocation-free) ----------------
__device__ float g_h   [MTOK*DIMV];
__device__ float g_ln  [MTOK*DIMV];
__device__ float g_qkv [MTOK*3*DIMV];
__device__ float g_o   [MTOK*DIMV];
__device__ float g_mlp [MTOK*HIDV];
__device__ float g_patch[MTOK*PINLEN];
__device__ float g_S   [33488928];  // 4*8*1023*1023

// ---------------- f32x2 helpers (FFMA2: 2 FMAs / instr on sm_103a) ----------------
__device__ __forceinline__ unsigned long long pack2(float lo, float hi) {
    unsigned long long r;
    asm("mov.b64 %0, {%1, %2};" : "=l"(r) : "f"(lo), "f"(hi));
    return r;
}
__device__ __forceinline__ unsigned long long fma2(unsigned long long a,
                                                   unsigned long long b,
                                                   unsigned long long c) {
    unsigned long long d;
    asm("fma.rn.f32x2 %0, %1, %2, %3;" : "=l"(d) : "l"(a), "l"(b), "l"(c));
    return d;
}
__device__ __forceinline__ void unpack2(unsigned long long v, float& lo, float& hi) {
    asm("mov.b64 {%0, %1}, %2;" : "=f"(lo), "=f"(hi) : "l"(v));
}

// ---------------- patch gather ----------------
// patches[b, p, c*16+t] = x[b, p*8+t, c]
__global__ void patch_kernel(const float* __restrict__ x, float* __restrict__ out) {
    int gid = blockIdx.x * blockDim.x + threadIdx.x;
    const int total = MTOK * PINLEN;
    if (gid >= total) return;
    int j = gid % PINLEN;
    int m = gid / PINLEN;
    int b = m / NPATCH;
    int p = m - b * NPATCH;
    int c = j >> 4;
    int t = j & 15;
    out[gid] = x[((size_t)b * SEQT + (size_t)p * 8 + t) * NCH + c];
}

// ---------------- layernorm over 512 ----------------
__global__ void ln_kernel(const float* __restrict__ in, const float* __restrict__ g,
                          const float* __restrict__ bb, float* __restrict__ out) {
    int row = blockIdx.x;
    int tid = threadIdx.x;                       // 128 threads, 1 float4 each
    const float4* xv = (const float4*)(in + (size_t)row * DIMV);
    float4 v = xv[tid];
    float s  = v.x + v.y + v.z + v.w;
    float s2 = v.x*v.x + v.y*v.y + v.z*v.z + v.w*v.w;
    #pragma unroll
    for (int o = 16; o > 0; o >>= 1) {
        s  += __shfl_xor_sync(0xFFFFFFFFu, s,  o);
        s2 += __shfl_xor_sync(0xFFFFFFFFu, s2, o);
    }
    __shared__ float sha[4], shb[4];
    int w = tid >> 5;
    if ((tid & 31) == 0) { sha[w] = s; shb[w] = s2; }
    __syncthreads();
    s  = sha[0] + sha[1] + sha[2] + sha[3];
    s2 = shb[0] + shb[1] + shb[2] + shb[3];
    float mu  = s * (1.0f / DIMV);
    float var = s2 * (1.0f / DIMV) - mu * mu;
    float rs  = rsqrtf(var + 1e-5f);
    float4 gg = ((const float4*)g)[tid];
    float4 bv = ((const float4*)bb)[tid];
    float4 o;
    o.x = (v.x - mu) * rs * gg.x + bv.x;
    o.y = (v.y - mu) * rs * gg.y + bv.y;
    o.z = (v.z - mu) * rs * gg.z + bv.z;
    o.w = (v.w - mu) * rs * gg.w + bv.w;
    ((float4*)(out + (size_t)row * DIMV))[tid] = o;
}

// ---------------- RoPE in-place on q,k inside qkv ----------------
__global__ void rope_kernel(float* __restrict__ qkv) {
    int gid = blockIdx.x * blockDim.x + threadIdx.x;
    const int total = MTOK * NHEAD * 32;
    if (gid >= total) return;
    int i = gid & 31;
    int h = (gid >> 5) & 7;
    int m = gid >> 8;
    int p = m % NPATCH;
    // inv_freq = 10000^(-i/32)
    float inv = expf(-(float)i * 0.28782313662425574f);   // ln(10000)/32
    float ang = (float)p * inv;
    float sv, cv;
    sincosf(ang, &sv, &cv);
    size_t base = (size_t)m * (3 * DIMV) + h * HDIM;
    // q
    float q0 = qkv[base + i], q1 = qkv[base + 32 + i];
    qkv[base + i]      = q0 * cv - q1 * sv;
    qkv[base + 32 + i] = q1 * cv + q0 * sv;
    // k
    size_t kb = base + DIMV;
    float k0 = qkv[kb + i], k1 = qkv[kb + 32 + i];
    qkv[kb + i]      = k0 * cv - k1 * sv;
    qkv[kb + 32 + i] = k1 * cv + k0 * sv;
}

// ---------------- row softmax (length n, scale folded) ----------------
__global__ void softmax_kernel(float* __restrict__ S, int n, float scale) {
    size_t row = blockIdx.x;
    float* p = S + row * (size_t)n;
    int tid = threadIdx.x;                        // 256 threads
    float v[4];
    float mx = -1e30f;
    #pragma unroll
    for (int t = 0; t < 4; t++) {
        int j = tid + t * 256;
        v[t] = (j < n) ? p[j] * scale : -1e30f;
        mx = fmaxf(mx, v[t]);
    }
    #pragma unroll
    for (int o = 16; o > 0; o >>= 1) mx = fmaxf(mx, __shfl_xor_sync(0xFFFFFFFFu, mx, o));
    __shared__ float sm1[8], sm2[8];
    if ((tid & 31) == 0) sm1[tid >> 5] = mx;
    __syncthreads();
    mx = sm1[0];
    #pragma unroll
    for (int w = 1; w < 8; w++) mx = fmaxf(mx, sm1[w]);
    float sum = 0.f;
    #pragma unroll
    for (int t = 0; t < 4; t++) {
        float e = __expf(v[t] - mx);
        v[t] = e;
        sum += e;
    }
    #pragma unroll
    for (int o = 16; o > 0; o >>= 1) sum += __shfl_xor_sync(0xFFFFFFFFu, sum, o);
    if ((tid & 31) == 0) sm2[tid >> 5] = sum;
    __syncthreads();
    sum = sm2[0] + sm2[1] + sm2[2] + sm2[3] + sm2[4] + sm2[5] + sm2[6] + sm2[7];
    float invs = 1.0f / sum;
    #pragma unroll
    for (int t = 0; t < 4; t++) {
        int j = tid + t * 256;
        if (j < n) p[j] = v[t] * invs;
    }
}

// ---------------- generic tiled fp32 GEMM with f32x2 accumulation ----------------
// C[z] = A[z] @ B[z] (+bias)(+gelu)(+res). Batch offset: z -> (z/nh)*s*b + (z%nh)*s*h.
// A row-major MxK (lda), B row-major KxN (ldb) or, if TRANSB, row-major NxK (B^T used).
template<bool TRANSB, bool BIAS, bool RES, bool GELU>
__global__ void __launch_bounds__(256)
gemm_f32(const float* __restrict__ A, int lda, long long sAb, long long sAh,
         const float* __restrict__ B, int ldb, long long sBb, long long sBh,
         const float* __restrict__ bias,
         const float* __restrict__ res,
         float* __restrict__ C, int ldc, long long sCb, long long sCh,
         int M, int N, int K, int nh)
{
    constexpr int BM = 128, BN = 128, BK = 16;
    __shared__ __align__(16) float As[BK][BM + 4];
    __shared__ __align__(16) float Bs[BK][BN + 4];

    int z  = blockIdx.z;
    int zb = z / nh, zh = z - zb * nh;
    A += zb * sAb + zh * sAh;
    B += zb * sBb + zh * sBh;
    C += zb * sCb + zh * sCh;
    if (RES) res += zb * sCb + zh * sCh;

    int tid = threadIdx.x;
    int tx = tid & 15, ty = tid >> 4;
    int row0 = blockIdx.y * BM;
    int col0 = blockIdx.x * BN;

    unsigned long long acc[8][4];
    #pragma unroll
    for (int i = 0; i < 8; i++)
        #pragma unroll
        for (int j = 0; j < 4; j++) acc[i][j] = 0ull;

    for (int k0 = 0; k0 < K; k0 += BK) {
        // ---- load A tile (transposed to As[k][m]) ----
        #pragma unroll
        for (int t = 0; t < 8; t++) {
            int idx = tid + t * 256;
            int m = idx >> 4, k = idx & 15;
            int gr = row0 + m, gk = k0 + k;
            float v = 0.f;
            if (gr < M && gk < K) v = A[(size_t)gr * lda + gk];
            As[k][m] = v;
        }
        // ---- load B tile into Bs[k][n] ----
        #pragma unroll
        for (int t = 0; t < 8; t++) {
            int idx = tid + t * 256;
            float v = 0.f;
            if (TRANSB) {
                int nn = idx >> 4, k = idx & 15;
                int gn = col0 + nn, gk = k0 + k;
                if (gn < N && gk < K) v = B[(size_t)gn * ldb + gk];
                Bs[k][nn] = v;
            } else {
                int k = idx >> 7, nn = idx & 127;
                int gn = col0 + nn, gk = k0 + k;
                if (gk < K && gn < N) v = B[(size_t)gk * ldb + gn];
                Bs[k][nn] = v;
            }
        }
        __syncthreads();
        // ---- compute 8x8 micro-tile, packed f32x2 ----
        #pragma unroll
        for (int k = 0; k < BK; k++) {
            float4 a0 = *(const float4*)&As[k][ty * 8];
            float4 a1 = *(const float4*)&As[k][ty * 8 + 4];
            float4 b0 = *(const float4*)&Bs[k][tx * 8];
            float4 b1 = *(const float4*)&Bs[k][tx * 8 + 4];
            unsigned long long bp0 = pack2(b0.x, b0.y);
            unsigned long long bp1 = pack2(b0.z, b0.w);
            unsigned long long bp2 = pack2(b1.x, b1.y);
            unsigned long long bp3 = pack2(b1.z, b1.w);
            float av[8] = {a0.x, a0.y, a0.z, a0.w, a1.x, a1.y, a1.z, a1.w};
            #pragma unroll
            for (int i = 0; i < 8; i++) {
                unsigned long long ap = pack2(av[i], av[i]);
                acc[i][0] = fma2(ap, bp0, acc[i][0]);
                acc[i][1] = fma2(ap, bp1, acc[i][1]);
                acc[i][2] = fma2(ap, bp2, acc[i][2]);
                acc[i][3] = fma2(ap, bp3, acc[i][3]);
            }
        }
        __syncthreads();
    }

    // ---- epilogue ----
    #pragma unroll
    for (int i = 0; i < 8; i++) {
        int gr = row0 + ty * 8 + i;
        if (gr < M) {
            size_t base = (size_t)gr * ldc;
            #pragma unroll
            for (int j = 0; j < 4; j++) {
                float c0, c1;
                unpack2(acc[i][j], c0, c1);
                int col = col0 + tx * 8 + j * 2;
                if (col < N) {
                    float v = c0;
                    if (BIAS) v += bias[col];
                    if (GELU) v = 0.5f * v * (1.0f + erff(v * 0.70710678118654752f));
                    if (RES)  v += res[base + col];
                    C[base + col] = v;
                }
                if (col + 1 < N) {
                    float v = c1;
                    if (BIAS) v += bias[col + 1];
                    if (GELU) v = 0.5f * v * (1.0f + erff(v * 0.70710678118654752f));
                    if (RES)  v += res[base + col + 1];
                    C[base + col + 1] = v;
                }
            }
        }
    }
}

// ---------------- host launch ----------------
static inline int cdiv(int a, int b) { return (a + b - 1) / b; }

extern "C" void kernel_launch(void* const* d_in, const int* in_sizes, int n_in,
                              void* d_out, int out_size) {
    const float* x      = (const float*)d_in[0];
    const float* W_emb  = (const float*)d_in[1];
    const float* b_emb  = (const float*)d_in[2];
    const float* ln1_g  = (const float*)d_in[3];
    const float* ln1_b  = (const float*)d_in[4];
    const float* W_qkv  = (const float*)d_in[5];
    const float* b_qkv  = (const float*)d_in[6];
    const float* W_proj = (const float*)d_in[7];
    const float* b_proj = (const float*)d_in[8];
    const float* ln2_g  = (const float*)d_in[9];
    const float* ln2_b  = (const float*)d_in[10];
    const float* W_mlp1 = (const float*)d_in[11];
    const float* b_mlp1 = (const float*)d_in[12];
    const float* W_mlp2 = (const float*)d_in[13];
    const float* b_mlp2 = (const float*)d_in[14];
    const float* lnf_g  = (const float*)d_in[15];
    const float* lnf_b  = (const float*)d_in[16];
    float* out = (float*)d_out;

    float *pH, *pLN, *pQKV, *pO, *pMLP, *pS, *pPatch;
    cudaGetSymbolAddress((void**)&pH,    g_h);
    cudaGetSymbolAddress((void**)&pLN,   g_ln);
    cudaGetSymbolAddress((void**)&pQKV,  g_qkv);
    cudaGetSymbolAddress((void**)&pO,    g_o);
    cudaGetSymbolAddress((void**)&pMLP,  g_mlp);
    cudaGetSymbolAddress((void**)&pS,    g_S);
    cudaGetSymbolAddress((void**)&pPatch,g_patch);

    const long long nn2 = (long long)NPATCH * NPATCH;

    // 1) patch gather
    patch_kernel<<<cdiv(MTOK * PINLEN, 256), 256>>>(x, pPatch);

    // 2) embedding GEMM: [4092,112] @ [112,512] + b -> h
    gemm_f32<false, true, false, false><<<dim3(cdiv(DIMV,128), cdiv(MTOK,128), 1), 256>>>(
        pPatch, PINLEN, 0, 0, W_emb, DIMV, 0, 0, b_emb, nullptr,
        pH, DIMV, 0, 0, MTOK, DIMV, PINLEN, 1);

    // emb output (first half of d_out)
    cudaMemcpyAsync(out, pH, (size_t)MTOK * DIMV * sizeof(float),
                    cudaMemcpyDeviceToDevice, 0);

    for (int L = 0; L < 4; L++) {
        // LN1
        ln_kernel<<<MTOK, 128>>>(pH, ln1_g + L * DIMV, ln1_b + L * DIMV, pLN);

        // QKV: [4092,512] @ [512,1536] + b
        gemm_f32<false, true, false, false><<<dim3(cdiv(3*DIMV,128), cdiv(MTOK,128), 1), 256>>>(
            pLN, DIMV, 0, 0, W_qkv + (size_t)L * DIMV * 3 * DIMV, 3 * DIMV, 0, 0,
            b_qkv + L * 3 * DIMV, nullptr, pQKV, 3 * DIMV, 0, 0, MTOK, 3 * DIMV, DIMV, 1);

        // RoPE on q,k
        rope_kernel<<<cdiv(MTOK * NHEAD * 32, 256), 256>>>(pQKV);

        // S = Q @ K^T  (32 batch-heads, M=N=1023, K=64)
        gemm_f32<true, false, false, false><<<dim3(cdiv(NPATCH,128), cdiv(NPATCH,128), 32), 256>>>(
            pQKV,        3 * DIMV, (long long)NPATCH * 3 * DIMV, HDIM,
            pQKV + DIMV, 3 * DIMV, (long long)NPATCH * 3 * DIMV, HDIM,
            nullptr, nullptr,
            pS, NPATCH, 8LL * nn2, nn2,
            NPATCH, NPATCH, HDIM, NHEAD);

        // softmax rows (scale = 1/sqrt(64))
        softmax_kernel<<<32 * NPATCH, 256>>>(pS, NPATCH, 0.125f);

        // O = P @ V  -> scatter into head-concat layout [4092,512]
        gemm_f32<false, false, false, false><<<dim3(1, cdiv(NPATCH,128), 32), 256>>>(
            pS, NPATCH, 8LL * nn2, nn2,
            pQKV + 2 * DIMV, 3 * DIMV, (long long)NPATCH * 3 * DIMV, HDIM,
            nullptr, nullptr,
            pO, DIMV, (long long)NPATCH * DIMV, HDIM,
            NPATCH, HDIM, NPATCH, NHEAD);

        // proj + residual: h = h + O @ W_proj + b
        gemm_f32<false, true, true, false><<<dim3(cdiv(DIMV,128), cdiv(MTOK,128), 1), 256>>>(
            pO, DIMV, 0, 0, W_proj + (size_t)L * DIMV * DIMV, DIMV, 0, 0,
            b_proj + L * DIMV, pH, pH, DIMV, 0, 0, MTOK, DIMV, DIMV, 1);

        // LN2
        ln_kernel<<<MTOK, 128>>>(pH, ln2_g + L * DIMV, ln2_b + L * DIMV, pLN);

        // MLP1 + GELU(exact)
        gemm_f32<false, true, false, true><<<dim3(cdiv(HIDV,128), cdiv(MTOK,128), 1), 256>>>(
            pLN, DIMV, 0, 0, W_mlp1 + (size_t)L * DIMV * HIDV, HIDV, 0, 0,
            b_mlp1 + L * HIDV, nullptr, pMLP, HIDV, 0, 0, MTOK, HIDV, DIMV, 1);

        // MLP2 + residual
        gemm_f32<false, true, true, false><<<dim3(cdiv(DIMV,128), cdiv(MTOK,128), 1), 256>>>(
            pMLP, HIDV, 0, 0, W_mlp2 + (size_t)L * HIDV * DIMV, DIMV, 0, 0,
            b_mlp2 + L * DIMV, pH, pH, DIMV, 0, 0, MTOK, DIMV, HIDV, 1);
    }

    // final LN -> second half of d_out
    ln_kernel<<<MTOK, 128>>>(pH, lnf_g, lnf_b, out + (size_t)MTOK * DIMV);
}

// round 5
// speedup vs baseline: 2.6405x; 2.6405x over previous
#include <cuda_runtime.h>
#include <cuda_bf16.h>
#include <math.h>

// ---------------- problem constants ----------------
#define BATCHN   4
#define SEQT     8192
#define NCH      7
#define NPATCH   1023               // (8192-16)/8+1
#define MTOK     (BATCHN*NPATCH)    // 4092
#define DIMV     512
#define HIDV     2048
#define NHEAD    8
#define HDIM     64
#define PINLEN   112                // PATCH_LEN*C = 16*7
#define SLD      1024               // padded row stride for S and V^T

// ---------------- device scratch (allocation-free) ----------------
__device__ __align__(256) float g_h    [MTOK*DIMV];
__device__ __align__(256) float g_ln   [MTOK*DIMV];
__device__ __align__(256) float g_qkv  [MTOK*3*DIMV];
__device__ __align__(256) float g_o    [MTOK*DIMV];
__device__ __align__(256) float g_mlp  [MTOK*HIDV];
__device__ __align__(256) float g_patch[MTOK*PINLEN];
__device__ __align__(256) float g_S    [32LL*NPATCH*SLD];   // scores, ld=1024
__device__ __align__(256) float g_vt   [32LL*HDIM*SLD];     // V^T per head, ld=1024
__device__ __align__(256) float g_wt   [12640256];          // all weights transposed [N][K]

// weight-transpose scratch offsets
#define OFF_EMB   0
#define OFF_QKV   57344
#define OFF_PROJ  3203072
#define OFF_MLP1  4251648
#define OFF_MLP2  8445952

// ---------------- patch gather ----------------
__global__ void patch_kernel(const float* __restrict__ x, float* __restrict__ out) {
    int gid = blockIdx.x * blockDim.x + threadIdx.x;
    const int total = MTOK * PINLEN;
    if (gid >= total) return;
    int j = gid % PINLEN;
    int m = gid / PINLEN;
    int b = m / NPATCH;
    int p = m - b * NPATCH;
    int c = j >> 4;
    int t = j & 15;
    out[gid] = x[((size_t)b * SEQT + (size_t)p * 8 + t) * NCH + c];
}

// ---------------- tiled transpose: out[c][r] = in[r][c], in is R x C ----------------
__global__ void transpose_kernel(const float* __restrict__ in, float* __restrict__ out,
                                 int R, int C) {
    __shared__ float t[32][33];
    int c0 = blockIdx.x * 32, r0 = blockIdx.y * 32;
    int tx = threadIdx.x, ty = threadIdx.y;   // 32 x 8
    #pragma unroll
    for (int i = 0; i < 32; i += 8) {
        int r = r0 + ty + i, c = c0 + tx;
        t[ty + i][tx] = (r < R && c < C) ? in[(size_t)r * C + c] : 0.f;
    }
    __syncthreads();
    #pragma unroll
    for (int i = 0; i < 32; i += 8) {
        int c = c0 + ty + i, r = r0 + tx;
        if (c < C && r < R) out[(size_t)c * R + r] = t[tx][ty + i];
    }
}

// ---------------- V^T per head: vt[z][d][p] = qkv[(b*NP+p)*1536 + 1024 + h*64 + d] ----
__global__ void vt_kernel(const float* __restrict__ qkv, float* __restrict__ vt) {
    __shared__ float t[32][33];
    int z = blockIdx.z; int b = z >> 3, h = z & 7;
    int p0 = blockIdx.x * 32, d0 = blockIdx.y * 32;
    int tx = threadIdx.x, ty = threadIdx.y;
    const float* src = qkv + (size_t)b * NPATCH * (3 * DIMV) + 2 * DIMV + h * HDIM;
    #pragma unroll
    for (int i = 0; i < 32; i += 8) {
        int p = p0 + ty + i; int d = d0 + tx;
        t[ty + i][tx] = (p < NPATCH) ? src[(size_t)p * (3 * DIMV) + d] : 0.f;
    }
    __syncthreads();
    float* dst = vt + (size_t)z * HDIM * SLD;
    #pragma unroll
    for (int i = 0; i < 32; i += 8) {
        int d = d0 + ty + i, p = p0 + tx;
        if (p < NPATCH) dst[(size_t)d * SLD + p] = t[tx][ty + i];
    }
}

// ---------------- layernorm over 512 ----------------
__global__ void ln_kernel(const float* __restrict__ in, const float* __restrict__ g,
                          const float* __restrict__ bb, float* __restrict__ out) {
    int row = blockIdx.x;
    int tid = threadIdx.x;                       // 128 threads, 1 float4 each
    const float4* xv = (const float4*)(in + (size_t)row * DIMV);
    float4 v = xv[tid];
    float s  = v.x + v.y + v.z + v.w;
    float s2 = v.x*v.x + v.y*v.y + v.z*v.z + v.w*v.w;
    #pragma unroll
    for (int o = 16; o > 0; o >>= 1) {
        s  += __shfl_xor_sync(0xFFFFFFFFu, s,  o);
        s2 += __shfl_xor_sync(0xFFFFFFFFu, s2, o);
    }
    __shared__ float sha[4], shb[4];
    int w = tid >> 5;
    if ((tid & 31) == 0) { sha[w] = s; shb[w] = s2; }
    __syncthreads();
    s  = sha[0] + sha[1] + sha[2] + sha[3];
    s2 = shb[0] + shb[1] + shb[2] + shb[3];
    float mu  = s * (1.0f / DIMV);
    float var = s2 * (1.0f / DIMV) - mu * mu;
    float rs  = rsqrtf(var + 1e-5f);
    float4 gg = ((const float4*)g)[tid];
    float4 bv = ((const float4*)bb)[tid];
    float4 o;
    o.x = (v.x - mu) * rs * gg.x + bv.x;
    o.y = (v.y - mu) * rs * gg.y + bv.y;
    o.z = (v.z - mu) * rs * gg.z + bv.z;
    o.w = (v.w - mu) * rs * gg.w + bv.w;
    ((float4*)(out + (size_t)row * DIMV))[tid] = o;
}

// ---------------- RoPE in-place on q,k inside qkv ----------------
__global__ void rope_kernel(float* __restrict__ qkv) {
    int gid = blockIdx.x * blockDim.x + threadIdx.x;
    const int total = MTOK * NHEAD * 32;
    if (gid >= total) return;
    int i = gid & 31;
    int h = (gid >> 5) & 7;
    int m = gid >> 8;
    int p = m % NPATCH;
    float inv = expf(-(float)i * 0.28782313662425574f);   // ln(10000)/32
    float ang = (float)p * inv;
    float sv, cv;
    sincosf(ang, &sv, &cv);
    size_t base = (size_t)m * (3 * DIMV) + h * HDIM;
    float q0 = qkv[base + i], q1 = qkv[base + 32 + i];
    qkv[base + i]      = q0 * cv - q1 * sv;
    qkv[base + 32 + i] = q1 * cv + q0 * sv;
    size_t kb = base + DIMV;
    float k0 = qkv[kb + i], k1 = qkv[kb + 32 + i];
    qkv[kb + i]      = k0 * cv - k1 * sv;
    qkv[kb + 32 + i] = k1 * cv + k0 * sv;
}

// ---------------- row softmax (length n, row stride SLD, scale folded) --------------
__global__ void softmax_kernel(float* __restrict__ S, int n, float scale) {
    size_t row = blockIdx.x;
    float* p = S + row * (size_t)SLD;
    int tid = threadIdx.x;                        // 256 threads
    float v[4];
    float mx = -1e30f;
    #pragma unroll
    for (int t = 0; t < 4; t++) {
        int j = tid + t * 256;
        v[t] = (j < n) ? p[j] * scale : -1e30f;
        mx = fmaxf(mx, v[t]);
    }
    #pragma unroll
    for (int o = 16; o > 0; o >>= 1) mx = fmaxf(mx, __shfl_xor_sync(0xFFFFFFFFu, mx, o));
    __shared__ float sm1[8], sm2[8];
    if ((tid & 31) == 0) sm1[tid >> 5] = mx;
    __syncthreads();
    mx = sm1[0];
    #pragma unroll
    for (int w = 1; w < 8; w++) mx = fmaxf(mx, sm1[w]);
    float sum = 0.f;
    #pragma unroll
    for (int t = 0; t < 4; t++) {
        float e = __expf(v[t] - mx);
        v[t] = e;
        sum += e;
    }
    #pragma unroll
    for (int o = 16; o > 0; o >>= 1) sum += __shfl_xor_sync(0xFFFFFFFFu, sum, o);
    if ((tid & 31) == 0) sm2[tid >> 5] = sum;
    __syncthreads();
    sum = sm2[0] + sm2[1] + sm2[2] + sm2[3] + sm2[4] + sm2[5] + sm2[6] + sm2[7];
    float invs = 1.0f / sum;
    #pragma unroll
    for (int t = 0; t < 4; t++) {
        int j = tid + t * 256;
        if (j < n) p[j] = v[t] * invs;
    }
}

// ---------------- bf16-split tensor-core GEMM ----------------
// C = A @ B^T where A is [M][K] row-major (lda) and B is [N][K] row-major (ldb).
// fp32 in/out; internally split to bf16 hi/lo, 3x mma.sync.m16n8k16 accumulation in fp32.
__device__ __forceinline__ void mma16816(float* d, const unsigned* a, const unsigned* b) {
    asm volatile(
        "mma.sync.aligned.m16n8k16.row.col.f32.bf16.bf16.f32 "
        "{%0,%1,%2,%3}, {%4,%5,%6,%7}, {%8,%9}, {%0,%1,%2,%3};"
        : "+f"(d[0]), "+f"(d[1]), "+f"(d[2]), "+f"(d[3])
        : "r"(a[0]), "r"(a[1]), "r"(a[2]), "r"(a[3]), "r"(b[0]), "r"(b[1]));
}

template<int BM, int BN, int WM, int WN, bool BIAS, bool RES, bool GELU>
__global__ void __launch_bounds__((BM/WM)*(BN/WN)*32)
gemm_tc(const float* __restrict__ A, int lda, long long sAb, long long sAh,
        const float* __restrict__ B, int ldb, long long sBb, long long sBh,
        const float* __restrict__ bias,
        const float* __restrict__ res,
        float* __restrict__ C, int ldc, long long sCb, long long sCh,
        int M, int N, int K, int nh)
{
    constexpr int BK = 32;
    constexpr int KP = 40;                         // padded k-dim (conflict-free)
    constexpr int NWM = BM / WM, NWN = BN / WN;
    constexpr int THREADS = NWM * NWN * 32;
    constexpr int MF = WM / 16, NF = WN / 8;
    constexpr int AV = BM * BK / (4 * THREADS);    // float4 A loads per thread
    constexpr int BV = BN * BK / (4 * THREADS);

    __shared__ __nv_bfloat16 Ah[BM][KP], Al[BM][KP], Bh[BN][KP], Bl[BN][KP];

    int z  = blockIdx.z;
    int zb = z / nh, zh = z - zb * nh;
    A += zb * sAb + zh * sAh;
    B += zb * sBb + zh * sBh;
    C += zb * sCb + zh * sCh;
    const float* resp = res;
    if (RES) resp += zb * sCb + zh * sCh;

    int tid  = threadIdx.x;
    int row0 = blockIdx.y * BM;
    int col0 = blockIdx.x * BN;

    float4 pa[AV], pb[BV];

    auto loadA = [&](int k0) {
        #pragma unroll
        for (int i = 0; i < AV; i++) {
            int p  = tid + i * THREADS;
            int r  = p >> 3;                       // BK/4 = 8 float4 per row
            int gk = k0 + (p & 7) * 4;
            int gr = row0 + r;
            float4 v = make_float4(0.f, 0.f, 0.f, 0.f);
            if (gr < M) {
                const float* ap = A + (size_t)gr * lda + gk;
                if (gk + 3 < K) v = *(const float4*)ap;
                else {
                    if (gk     < K) v.x = ap[0];
                    if (gk + 1 < K) v.y = ap[1];
                    if (gk + 2 < K) v.z = ap[2];
                }
            }
            pa[i] = v;
        }
    };
    auto loadB = [&](int k0) {
        #pragma unroll
        for (int i = 0; i < BV; i++) {
            int p  = tid + i * THREADS;
            int r  = p >> 3;
            int gk = k0 + (p & 7) * 4;
            int gn = col0 + r;
            float4 v = make_float4(0.f, 0.f, 0.f, 0.f);
            if (gn < N) {
                const float* bp = B + (size_t)gn * ldb + gk;
                if (gk + 3 < K) v = *(const float4*)bp;
                else {
                    if (gk     < K) v.x = bp[0];
                    if (gk + 1 < K) v.y = bp[1];
                    if (gk + 2 < K) v.z = bp[2];
                }
            }
            pb[i] = v;
        }
    };

    auto splitStore = [&](float4 v, __nv_bfloat16* hdst, __nv_bfloat16* ldst) {
        union { unsigned long long u; __nv_bfloat16 h[4]; } wh, wl;
        float e[4] = {v.x, v.y, v.z, v.w};
        #pragma unroll
        for (int q = 0; q < 4; q++) {
            __nv_bfloat16 hb = __float2bfloat16_rn(e[q]);
            wh.h[q] = hb;
            wl.h[q] = __float2bfloat16_rn(e[q] - __bfloat162float(hb));
        }
        *(unsigned long long*)hdst = wh.u;
        *(unsigned long long*)ldst = wl.u;
    };

    int wid  = tid >> 5, lane = tid & 31;
    int wm   = wid % NWM, wn = wid / NWM;
    int wrow = wm * WM, wcol = wn * WN;

    float acc[MF][NF][4];
    #pragma unroll
    for (int mi = 0; mi < MF; mi++)
        #pragma unroll
        for (int ni = 0; ni < NF; ni++)
            #pragma unroll
            for (int e = 0; e < 4; e++) acc[mi][ni][e] = 0.f;

    int nk = (K + BK - 1) / BK;
    loadA(0);
    loadB(0);

    for (int kt = 0; kt < nk; kt++) {
        // commit prefetched tile to smem (bf16 split)
        #pragma unroll
        for (int i = 0; i < AV; i++) {
            int p = tid + i * THREADS;
            int r = p >> 3, c4 = (p & 7) * 4;
            splitStore(pa[i], &Ah[r][c4], &Al[r][c4]);
        }
        #pragma unroll
        for (int i = 0; i < BV; i++) {
            int p = tid + i * THREADS;
            int r = p >> 3, c4 = (p & 7) * 4;
            splitStore(pb[i], &Bh[r][c4], &Bl[r][c4]);
        }
        __syncthreads();

        if (kt + 1 < nk) { loadA((kt + 1) * BK); loadB((kt + 1) * BK); }

        int rfr = lane >> 2, c2 = (lane & 3) * 2;
        #pragma unroll
        for (int kk = 0; kk < 2; kk++) {
            int kb = kk * 16 + c2;
            unsigned ah[MF][4], al[MF][4], bh[NF][2], bl[NF][2];
            #pragma unroll
            for (int mi = 0; mi < MF; mi++) {
                int rr = wrow + mi * 16 + rfr;
                ah[mi][0] = *(const unsigned*)&Ah[rr    ][kb    ];
                ah[mi][1] = *(const unsigned*)&Ah[rr + 8][kb    ];
                ah[mi][2] = *(const unsigned*)&Ah[rr    ][kb + 8];
                ah[mi][3] = *(const unsigned*)&Ah[rr + 8][kb + 8];
                al[mi][0] = *(const unsigned*)&Al[rr    ][kb    ];
                al[mi][1] = *(const unsigned*)&Al[rr + 8][kb    ];
                al[mi][2] = *(const unsigned*)&Al[rr    ][kb + 8];
                al[mi][3] = *(const unsigned*)&Al[rr + 8][kb + 8];
            }
            #pragma unroll
            for (int ni = 0; ni < NF; ni++) {
                int nn = wcol + ni * 8 + rfr;
                bh[ni][0] = *(const unsigned*)&Bh[nn][kb    ];
                bh[ni][1] = *(const unsigned*)&Bh[nn][kb + 8];
                bl[ni][0] = *(const unsigned*)&Bl[nn][kb    ];
                bl[ni][1] = *(const unsigned*)&Bl[nn][kb + 8];
            }
            #pragma unroll
            for (int mi = 0; mi < MF; mi++)
                #pragma unroll
                for (int ni = 0; ni < NF; ni++) {
                    mma16816(acc[mi][ni], ah[mi], bh[ni]);
                    mma16816(acc[mi][ni], ah[mi], bl[ni]);
                    mma16816(acc[mi][ni], al[mi], bh[ni]);
                }
        }
        __syncthreads();
    }

    // epilogue
    #pragma unroll
    for (int mi = 0; mi < MF; mi++) {
        #pragma unroll
        for (int ni = 0; ni < NF; ni++) {
            int rr0 = row0 + wrow + mi * 16 + (lane >> 2);
            int cc0 = col0 + wcol + ni * 8 + (lane & 3) * 2;
            #pragma unroll
            for (int e = 0; e < 4; e++) {
                int rr = rr0 + ((e >= 2) ? 8 : 0);
                int cc = cc0 + (e & 1);
                if (rr < M && cc < N) {
                    float v = acc[mi][ni][e];
                    if (BIAS) v += bias[cc];
                    if (GELU) v = 0.5f * v * (1.0f + erff(v * 0.70710678118654752f));
                    if (RES)  v += resp[(size_t)rr * ldc + cc];
                    C[(size_t)rr * ldc + cc] = v;
                }
            }
        }
    }
}

// ---------------- host launch ----------------
static inline int cdiv(int a, int b) { return (a + b - 1) / b; }

extern "C" void kernel_launch(void* const* d_in, const int* in_sizes, int n_in,
                              void* d_out, int out_size) {
    const float* x      = (const float*)d_in[0];
    const float* W_emb  = (const float*)d_in[1];
    const float* b_emb  = (const float*)d_in[2];
    const float* ln1_g  = (const float*)d_in[3];
    const float* ln1_b  = (const float*)d_in[4];
    const float* W_qkv  = (const float*)d_in[5];
    const float* b_qkv  = (const float*)d_in[6];
    const float* W_proj = (const float*)d_in[7];
    const float* b_proj = (const float*)d_in[8];
    const float* ln2_g  = (const float*)d_in[9];
    const float* ln2_b  = (const float*)d_in[10];
    const float* W_mlp1 = (const float*)d_in[11];
    const float* b_mlp1 = (const float*)d_in[12];
    const float* W_mlp2 = (const float*)d_in[13];
    const float* b_mlp2 = (const float*)d_in[14];
    const float* lnf_g  = (const float*)d_in[15];
    const float* lnf_b  = (const float*)d_in[16];
    float* out = (float*)d_out;

    float *pH, *pLN, *pQKV, *pO, *pMLP, *pS, *pPatch, *pVT, *pWT;
    cudaGetSymbolAddress((void**)&pH,    g_h);
    cudaGetSymbolAddress((void**)&pLN,   g_ln);
    cudaGetSymbolAddress((void**)&pQKV,  g_qkv);
    cudaGetSymbolAddress((void**)&pO,    g_o);
    cudaGetSymbolAddress((void**)&pMLP,  g_mlp);
    cudaGetSymbolAddress((void**)&pS,    g_S);
    cudaGetSymbolAddress((void**)&pPatch,g_patch);
    cudaGetSymbolAddress((void**)&pVT,   g_vt);
    cudaGetSymbolAddress((void**)&pWT,   g_wt);

    dim3 tb(32, 8);

    // 0) transpose all weights to [N][K] once
    transpose_kernel<<<dim3(cdiv(DIMV,32), cdiv(PINLEN,32)), tb>>>(W_emb, pWT + OFF_EMB, PINLEN, DIMV);
    for (int L = 0; L < 4; L++) {
        transpose_kernel<<<dim3(cdiv(3*DIMV,32), cdiv(DIMV,32)), tb>>>(
            W_qkv + (size_t)L*DIMV*3*DIMV, pWT + OFF_QKV + (size_t)L*3*DIMV*DIMV, DIMV, 3*DIMV);
        transpose_kernel<<<dim3(cdiv(DIMV,32), cdiv(DIMV,32)), tb>>>(
            W_proj + (size_t)L*DIMV*DIMV, pWT + OFF_PROJ + (size_t)L*DIMV*DIMV, DIMV, DIMV);
        transpose_kernel<<<dim3(cdiv(HIDV,32), cdiv(DIMV,32)), tb>>>(
            W_mlp1 + (size_t)L*DIMV*HIDV, pWT + OFF_MLP1 + (size_t)L*DIMV*HIDV, DIMV, HIDV);
        transpose_kernel<<<dim3(cdiv(DIMV,32), cdiv(HIDV,32)), tb>>>(
            W_mlp2 + (size_t)L*HIDV*DIMV, pWT + OFF_MLP2 + (size_t)L*HIDV*DIMV, HIDV, DIMV);
    }

    // 1) patch gather
    patch_kernel<<<cdiv(MTOK * PINLEN, 256), 256>>>(x, pPatch);

    // 2) embedding: [4092,112] @ WT_emb[512][112]^T + b -> h
    gemm_tc<128,128,64,32, true,false,false><<<dim3(cdiv(DIMV,128), cdiv(MTOK,128), 1), 256>>>(
        pPatch, PINLEN, 0, 0, pWT + OFF_EMB, PINLEN, 0, 0, b_emb, nullptr,
        pH, DIMV, 0, 0, MTOK, DIMV, PINLEN, 1);

    cudaMemcpyAsync(out, pH, (size_t)MTOK * DIMV * sizeof(float),
                    cudaMemcpyDeviceToDevice, 0);

    const long long sQb = (long long)NPATCH * 3 * DIMV;   // batch stride inside qkv
    const long long sSb = 8LL * NPATCH * SLD;
    const long long sSh = (long long)NPATCH * SLD;

    for (int L = 0; L < 4; L++) {
        ln_kernel<<<MTOK, 128>>>(pH, ln1_g + L*DIMV, ln1_b + L*DIMV, pLN);

        // QKV: [4092,512] @ WT_qkv[1536][512]^T + b
        gemm_tc<128,128,64,32, true,false,false><<<dim3(cdiv(3*DIMV,128), cdiv(MTOK,128), 1), 256>>>(
            pLN, DIMV, 0, 0, pWT + OFF_QKV + (size_t)L*3*DIMV*DIMV, DIMV, 0, 0,
            b_qkv + L*3*DIMV, nullptr, pQKV, 3*DIMV, 0, 0, MTOK, 3*DIMV, DIMV, 1);

        rope_kernel<<<cdiv(MTOK * NHEAD * 32, 256), 256>>>(pQKV);

        // V^T per head (ld 1024)
        vt_kernel<<<dim3(32, 2, 32), tb>>>(pQKV, pVT);

        // S = Q @ K^T  (32 batch-heads, M=N=1023, K=64), C row stride 1024
        gemm_tc<128,128,64,32, false,false,false><<<dim3(8, 8, 32), 256>>>(
            pQKV,        3*DIMV, sQb, HDIM,
            pQKV + DIMV, 3*DIMV, sQb, HDIM,
            nullptr, nullptr,
            pS, SLD, sSb, sSh,
            NPATCH, NPATCH, HDIM, NHEAD);

        softmax_kernel<<<32 * NPATCH, 256>>>(pS, NPATCH, 0.125f);

        // O = P @ V : A = S [1023][1023] (ld 1024), B = V^T [64][1023] (ld 1024)
        gemm_tc<128,64,64,32, false,false,false><<<dim3(1, 8, 32), 128>>>(
            pS, SLD, sSb, sSh,
            pVT, SLD, 8LL*HDIM*SLD, (long long)HDIM*SLD,
            nullptr, nullptr,
            pO, DIMV, (long long)NPATCH*DIMV, HDIM,
            NPATCH, HDIM, NPATCH, NHEAD);

        // proj + residual
        gemm_tc<128,128,64,32, true,true,false><<<dim3(cdiv(DIMV,128), cdiv(MTOK,128), 1), 256>>>(
            pO, DIMV, 0, 0, pWT + OFF_PROJ + (size_t)L*DIMV*DIMV, DIMV, 0, 0,
            b_proj + L*DIMV, pH, pH, DIMV, 0, 0, MTOK, DIMV, DIMV, 1);

        ln_kernel<<<MTOK, 128>>>(pH, ln2_g + L*DIMV, ln2_b + L*DIMV, pLN);

        // MLP1 + GELU
        gemm_tc<128,128,64,32, true,false,true><<<dim3(cdiv(HIDV,128), cdiv(MTOK,128), 1), 256>>>(
            pLN, DIMV, 0, 0, pWT + OFF_MLP1 + (size_t)L*DIMV*HIDV, DIMV, 0, 0,
            b_mlp1 + L*HIDV, nullptr, pMLP, HIDV, 0, 0, MTOK, HIDV, DIMV, 1);

        // MLP2 + residual
        gemm_tc<128,128,64,32, true,true,false><<<dim3(cdiv(DIMV,128), cdiv(MTOK,128), 1), 256>>>(
            pMLP, HIDV, 0, 0, pWT + OFF_MLP2 + (size_t)L*HIDV*DIMV, HIDV, 0, 0,
            b_mlp2 + L*DIMV, pH, pH, DIMV, 0, 0, MTOK, DIMV, HIDV, 1);
    }

    ln_kernel<<<MTOK, 128>>>(pH, lnf_g, lnf_b, out + (size_t)MTOK * DIMV);
}

// round 6
// speedup vs baseline: 3.3085x; 1.2530x over previous
#include <cuda_runtime.h>
#include <cuda_bf16.h>
#include <math.h>

typedef __nv_bfloat16 BF;

// ---------------- problem constants ----------------
#define BATCHN   4
#define SEQT     8192
#define NCH      7
#define NPATCH   1023               // (8192-16)/8+1
#define MTOK     (BATCHN*NPATCH)    // 4092
#define DIMV     512
#define HIDV     2048
#define NHEAD    8
#define HDIM     64
#define PINLEN   112                // PATCH_LEN*C = 16*7
#define SLD      1024               // padded attention K / row stride

// ---------------- device scratch (allocation-free) ----------------
__device__ __align__(256) float g_h    [MTOK*DIMV];       // residual stream fp32
__device__ __align__(256) float g_qkv  [MTOK*3*DIMV];     // fp32 qkv (pre-rope)
__device__ __align__(256) float g_S    [32LL*NPATCH*SLD]; // fp32 scores
// bf16 hi/lo planes
__device__ __align__(256) BF g_ln_h [MTOK*DIMV],     g_ln_l [MTOK*DIMV];
__device__ __align__(256) BF g_qk_h [MTOK*3*DIMV],   g_qk_l [MTOK*3*DIMV];   // rope'd q,k planes (V region unused)
__device__ __align__(256) BF g_o_h  [MTOK*DIMV],     g_o_l  [MTOK*DIMV];
__device__ __align__(256) BF g_mlp_h[MTOK*HIDV],     g_mlp_l[MTOK*HIDV];
__device__ __align__(256) BF g_pt_h [MTOK*PINLEN],   g_pt_l [MTOK*PINLEN];
__device__ __align__(256) BF g_p_h  [32LL*NPATCH*SLD], g_p_l[32LL*NPATCH*SLD]; // softmax planes
__device__ __align__(256) BF g_vt_h [32LL*HDIM*SLD], g_vt_l [32LL*HDIM*SLD];   // V^T planes
__device__ __align__(256) BF g_wt_h [12640256],      g_wt_l [12640256];        // transposed weights [N][K]

// weight-transpose scratch offsets (elements)
#define OFF_EMB   0
#define OFF_QKV   57344
#define OFF_PROJ  3203072
#define OFF_MLP1  4251648
#define OFF_MLP2  8445952

// ---------------- helpers ----------------
__device__ __forceinline__ void fsplit(float v, BF& h, BF& l) {
    h = __float2bfloat16_rn(v);
    l = __float2bfloat16_rn(v - __bfloat162float(h));
}
__device__ __forceinline__ unsigned cvta_s(const void* p) {
    return (unsigned)__cvta_generic_to_shared(p);
}
__device__ __forceinline__ void cp16(unsigned dst, const void* src, bool pred) {
    int sz = pred ? 16 : 0;
    asm volatile("cp.async.cg.shared.global [%0], [%1], 16, %2;\n"
                 :: "r"(dst), "l"(src), "r"(sz));
}
__device__ __forceinline__ void cp_commit() { asm volatile("cp.async.commit_group;\n"); }
__device__ __forceinline__ void cp_wait0()  { asm volatile("cp.async.wait_group 0;\n"); }

__device__ __forceinline__ void mma16816(float* d, const unsigned* a, const unsigned* b) {
    asm volatile(
        "mma.sync.aligned.m16n8k16.row.col.f32.bf16.bf16.f32 "
        "{%0,%1,%2,%3}, {%4,%5,%6,%7}, {%8,%9}, {%0,%1,%2,%3};"
        : "+f"(d[0]), "+f"(d[1]), "+f"(d[2]), "+f"(d[3])
        : "r"(a[0]), "r"(a[1]), "r"(a[2]), "r"(a[3]), "r"(b[0]), "r"(b[1]));
}

// ---------------- patch gather -> planes ----------------
__global__ void patch_kernel(const float* __restrict__ x, BF* __restrict__ oh, BF* __restrict__ ol) {
    int gid = blockIdx.x * blockDim.x + threadIdx.x;
    const int total = MTOK * PINLEN;
    if (gid >= total) return;
    int j = gid % PINLEN;
    int m = gid / PINLEN;
    int b = m / NPATCH;
    int p = m - b * NPATCH;
    int c = j >> 4;
    int t = j & 15;
    float v = x[((size_t)b * SEQT + (size_t)p * 8 + t) * NCH + c];
    fsplit(v, oh[gid], ol[gid]);
}

// ---------------- weight transpose -> planes: out[c][r] = in[r][c], in R x C ------
__global__ void transpose_kernel(const float* __restrict__ in, BF* __restrict__ oh,
                                 BF* __restrict__ ol, int R, int C) {
    __shared__ float t[32][33];
    int c0 = blockIdx.x * 32, r0 = blockIdx.y * 32;
    int tx = threadIdx.x, ty = threadIdx.y;   // 32 x 8
    #pragma unroll
    for (int i = 0; i < 32; i += 8) {
        int r = r0 + ty + i, c = c0 + tx;
        t[ty + i][tx] = (r < R && c < C) ? in[(size_t)r * C + c] : 0.f;
    }
    __syncthreads();
    #pragma unroll
    for (int i = 0; i < 32; i += 8) {
        int c = c0 + ty + i, r = r0 + tx;
        if (c < C && r < R) {
            size_t d = (size_t)c * R + r;
            fsplit(t[tx][ty + i], oh[d], ol[d]);
        }
    }
}

// ---------------- V^T planes: vt[z][d][p] = qkv[(b*NP+p)*1536 + 1024 + h*64 + d] ----
__global__ void vt_kernel(const float* __restrict__ qkv, BF* __restrict__ vh, BF* __restrict__ vl) {
    __shared__ float t[32][33];
    int z = blockIdx.z; int b = z >> 3, h = z & 7;
    int p0 = blockIdx.x * 32, d0 = blockIdx.y * 32;
    int tx = threadIdx.x, ty = threadIdx.y;
    const float* src = qkv + (size_t)b * NPATCH * (3 * DIMV) + 2 * DIMV + h * HDIM;
    #pragma unroll
    for (int i = 0; i < 32; i += 8) {
        int p = p0 + ty + i; int d = d0 + tx;
        t[ty + i][tx] = (p < NPATCH) ? src[(size_t)p * (3 * DIMV) + d] : 0.f;
    }
    __syncthreads();
    size_t zb = (size_t)z * HDIM * SLD;
    #pragma unroll
    for (int i = 0; i < 32; i += 8) {
        int d = d0 + ty + i, p = p0 + tx;
        size_t dst = zb + (size_t)d * SLD + p;           // p < 1024 always
        fsplit(t[tx][ty + i], vh[dst], vl[dst]);         // p==1023 -> 0 (zero pad)
    }
}

// ---------------- layernorm over 512: fp32 in; out planes OR fp32 ----------------
template<bool PLANES>
__global__ void ln_kernel(const float* __restrict__ in, const float* __restrict__ g,
                          const float* __restrict__ bb,
                          float* __restrict__ outf, BF* __restrict__ oh, BF* __restrict__ ol) {
    int row = blockIdx.x;
    int tid = threadIdx.x;                       // 128 threads, 1 float4 each
    const float4* xv = (const float4*)(in + (size_t)row * DIMV);
    float4 v = xv[tid];
    float s  = v.x + v.y + v.z + v.w;
    float s2 = v.x*v.x + v.y*v.y + v.z*v.z + v.w*v.w;
    #pragma unroll
    for (int o = 16; o > 0; o >>= 1) {
        s  += __shfl_xor_sync(0xFFFFFFFFu, s,  o);
        s2 += __shfl_xor_sync(0xFFFFFFFFu, s2, o);
    }
    __shared__ float sha[4], shb[4];
    int w = tid >> 5;
    if ((tid & 31) == 0) { sha[w] = s; shb[w] = s2; }
    __syncthreads();
    s  = sha[0] + sha[1] + sha[2] + sha[3];
    s2 = shb[0] + shb[1] + shb[2] + shb[3];
    float mu  = s * (1.0f / DIMV);
    float var = s2 * (1.0f / DIMV) - mu * mu;
    float rs  = rsqrtf(var + 1e-5f);
    float4 gg = ((const float4*)g)[tid];
    float4 bv = ((const float4*)bb)[tid];
    float o0 = (v.x - mu) * rs * gg.x + bv.x;
    float o1 = (v.y - mu) * rs * gg.y + bv.y;
    float o2 = (v.z - mu) * rs * gg.z + bv.z;
    float o3 = (v.w - mu) * rs * gg.w + bv.w;
    if (PLANES) {
        union { unsigned long long u; BF b[4]; } uh, ul;
        fsplit(o0, uh.b[0], ul.b[0]);
        fsplit(o1, uh.b[1], ul.b[1]);
        fsplit(o2, uh.b[2], ul.b[2]);
        fsplit(o3, uh.b[3], ul.b[3]);
        *(unsigned long long*)(oh + (size_t)row * DIMV + tid * 4) = uh.u;
        *(unsigned long long*)(ol + (size_t)row * DIMV + tid * 4) = ul.u;
    } else {
        float4 o = make_float4(o0, o1, o2, o3);
        ((float4*)(outf + (size_t)row * DIMV))[tid] = o;
    }
}

// ---------------- RoPE: read fp32 qkv, write rotated q,k planes ----------------
__global__ void rope_kernel(const float* __restrict__ qkv, BF* __restrict__ qh, BF* __restrict__ ql) {
    int gid = blockIdx.x * blockDim.x + threadIdx.x;
    const int total = MTOK * NHEAD * 32;
    if (gid >= total) return;
    int i = gid & 31;
    int h = (gid >> 5) & 7;
    int m = gid >> 8;
    int p = m % NPATCH;
    float inv = expf(-(float)i * 0.28782313662425574f);   // ln(10000)/32
    float ang = (float)p * inv;
    float sv, cv;
    sincosf(ang, &sv, &cv);
    size_t base = (size_t)m * (3 * DIMV) + h * HDIM;
    float q0 = qkv[base + i], q1 = qkv[base + 32 + i];
    fsplit(q0 * cv - q1 * sv, qh[base + i],      ql[base + i]);
    fsplit(q1 * cv + q0 * sv, qh[base + 32 + i], ql[base + 32 + i]);
    size_t kb = base + DIMV;
    float k0 = qkv[kb + i], k1 = qkv[kb + 32 + i];
    fsplit(k0 * cv - k1 * sv, qh[kb + i],      ql[kb + i]);
    fsplit(k1 * cv + k0 * sv, qh[kb + 32 + i], ql[kb + 32 + i]);
}

// ---------------- softmax: fp32 S (ld SLD) -> bf16 P planes, zero-padded to SLD ----
__global__ void softmax_kernel(const float* __restrict__ S, BF* __restrict__ ph,
                               BF* __restrict__ pl, int n, float scale) {
    size_t row = blockIdx.x;
    const float* p = S + row * (size_t)SLD;
    int tid = threadIdx.x;                        // 256 threads
    float v[4];
    float mx = -1e30f;
    #pragma unroll
    for (int t = 0; t < 4; t++) {
        int j = tid + t * 256;
        v[t] = (j < n) ? p[j] * scale : -1e30f;
        mx = fmaxf(mx, v[t]);
    }
    #pragma unroll
    for (int o = 16; o > 0; o >>= 1) mx = fmaxf(mx, __shfl_xor_sync(0xFFFFFFFFu, mx, o));
    __shared__ float sm1[8], sm2[8];
    if ((tid & 31) == 0) sm1[tid >> 5] = mx;
    __syncthreads();
    mx = sm1[0];
    #pragma unroll
    for (int w = 1; w < 8; w++) mx = fmaxf(mx, sm1[w]);
    float sum = 0.f;
    #pragma unroll
    for (int t = 0; t < 4; t++) {
        float e = __expf(v[t] - mx);
        v[t] = e;
        sum += e;
    }
    #pragma unroll
    for (int o = 16; o > 0; o >>= 1) sum += __shfl_xor_sync(0xFFFFFFFFu, sum, o);
    if ((tid & 31) == 0) sm2[tid >> 5] = sum;
    __syncthreads();
    sum = sm2[0] + sm2[1] + sm2[2] + sm2[3] + sm2[4] + sm2[5] + sm2[6] + sm2[7];
    float invs = 1.0f / sum;
    BF* oh = ph + row * (size_t)SLD;
    BF* ol = pl + row * (size_t)SLD;
    #pragma unroll
    for (int t = 0; t < 4; t++) {
        int j = tid + t * 256;
        float val = (j < n) ? v[t] * invs : 0.f;
        fsplit(val, oh[j], ol[j]);
    }
}

// ---------------- bf16-plane tensor-core GEMM, cp.async 2-stage pipeline ----------
// C = A @ B^T. A: [M][K] planes (lda), B: [N][K] planes (ldb). 3-MMA hi/lo split.
template<int BM, int BN, int WM, int WN, bool BIAS, bool RES, bool GELU, bool PLANES>
__global__ void __launch_bounds__((BM/WM)*(BN/WN)*32)
gemm_bf(const BF* __restrict__ Ah_g, const BF* __restrict__ Al_g, int lda, long long sAb, long long sAh,
        const BF* __restrict__ Bh_g, const BF* __restrict__ Bl_g, int ldb, long long sBb, long long sBh,
        const float* __restrict__ bias, const float* __restrict__ res,
        float* __restrict__ C, BF* __restrict__ Ch, BF* __restrict__ Cl,
        int ldc, long long sCb, long long sCh,
        int M, int N, int K, int nh)
{
    constexpr int BK = 32, KP = 40;                 // 80-byte rows, conflict-free LDS
    constexpr int NWM = BM / WM, NWN = BN / WN;
    constexpr int THREADS = NWM * NWN * 32;
    constexpr int MF = WM / 16, NF = WN / 8;
    constexpr int CA = BM * (BK / 8) * 2;           // 16B chunks per stage (A, both planes)
    constexpr int CB = BN * (BK / 8) * 2;
    constexpr int TA = CA / THREADS, TB = CB / THREADS;
    constexpr int ROWB = KP * 2;                    // 80 bytes per row
    constexpr int OFF_AL_ = BM * ROWB;
    constexpr int OFF_BH_ = 2 * BM * ROWB;
    constexpr int OFF_BL_ = 2 * BM * ROWB + BN * ROWB;
    constexpr int STAGE = 2 * BM * ROWB + 2 * BN * ROWB;

    extern __shared__ char smraw[];

    int z  = blockIdx.z;
    int zb = z / nh, zh = z - zb * nh;
    Ah_g += zb * sAb + zh * sAh;  Al_g += zb * sAb + zh * sAh;
    Bh_g += zb * sBb + zh * sBh;  Bl_g += zb * sBb + zh * sBh;
    long long coff = zb * sCb + zh * sCh;
    if (!PLANES) { C += coff; if (RES) res += coff; }
    else         { Ch += coff; Cl += coff; }

    int tid  = threadIdx.x;
    int row0 = blockIdx.y * BM;
    int col0 = blockIdx.x * BN;
    unsigned sbase0 = cvta_s(smraw);

    auto issue = [&](int kt, int stage) {
        int k0 = kt * BK;
        unsigned sb = sbase0 + stage * STAGE;
        #pragma unroll
        for (int i = 0; i < TA; i++) {
            int idx = tid + i * THREADS;
            bool lo = idx >= CA / 2;
            int id2 = lo ? idx - CA / 2 : idx;
            int r = id2 >> 2, ch = id2 & 3;
            int gk = k0 + ch * 8;
            int gr = row0 + r;
            bool ok = (gr < M) && (gk < K);
            int grc = ok ? gr : 0;
            const BF* src = (lo ? Al_g : Ah_g) + (size_t)grc * lda + (gk < K ? gk : 0);
            cp16(sb + (lo ? OFF_AL_ : 0) + r * ROWB + ch * 16, src, ok);
        }
        #pragma unroll
        for (int i = 0; i < TB; i++) {
            int idx = tid + i * THREADS;
            bool lo = idx >= CB / 2;
            int id2 = lo ? idx - CB / 2 : idx;
            int r = id2 >> 2, ch = id2 & 3;
            int gk = k0 + ch * 8;
            int gn = col0 + r;
            bool ok = (gn < N) && (gk < K);
            int gnc = ok ? gn : 0;
            const BF* src = (lo ? Bl_g : Bh_g) + (size_t)gnc * ldb + (gk < K ? gk : 0);
            cp16(sb + (lo ? OFF_BL_ : OFF_BH_) + r * ROWB + ch * 16, src, ok);
        }
        cp_commit();
    };

    int wid  = tid >> 5, lane = tid & 31;
    int wm   = wid % NWM, wn = wid / NWM;
    int wrow = wm * WM, wcol = wn * WN;
    int rfr  = lane >> 2, c2 = (lane & 3) * 2;

    float acc[MF][NF][4];
    #pragma unroll
    for (int mi = 0; mi < MF; mi++)
        #pragma unroll
        for (int ni = 0; ni < NF; ni++)
            #pragma unroll
            for (int e = 0; e < 4; e++) acc[mi][ni][e] = 0.f;

    int nk = (K + BK - 1) / BK;
    issue(0, 0);

    for (int kt = 0; kt < nk; kt++) {
        cp_wait0();
        __syncthreads();
        if (kt + 1 < nk) issue(kt + 1, (kt + 1) & 1);

        const char* st = smraw + (kt & 1) * STAGE;
        const BF* Ah = (const BF*)st;
        const BF* Al = (const BF*)(st + OFF_AL_);
        const BF* Bh = (const BF*)(st + OFF_BH_);
        const BF* Bl = (const BF*)(st + OFF_BL_);

        #pragma unroll
        for (int kk = 0; kk < 2; kk++) {
            int kb = kk * 16 + c2;
            unsigned ah[MF][4], al[MF][4], bh[NF][2], bl[NF][2];
            #pragma unroll
            for (int mi = 0; mi < MF; mi++) {
                int rr = wrow + mi * 16 + rfr;
                ah[mi][0] = *(const unsigned*)&Ah[(rr    ) * KP + kb    ];
                ah[mi][1] = *(const unsigned*)&Ah[(rr + 8) * KP + kb    ];
                ah[mi][2] = *(const unsigned*)&Ah[(rr    ) * KP + kb + 8];
                ah[mi][3] = *(const unsigned*)&Ah[(rr + 8) * KP + kb + 8];
                al[mi][0] = *(const unsigned*)&Al[(rr    ) * KP + kb    ];
                al[mi][1] = *(const unsigned*)&Al[(rr + 8) * KP + kb    ];
                al[mi][2] = *(const unsigned*)&Al[(rr    ) * KP + kb + 8];
                al[mi][3] = *(const unsigned*)&Al[(rr + 8) * KP + kb + 8];
            }
            #pragma unroll
            for (int ni = 0; ni < NF; ni++) {
                int nn = wcol + ni * 8 + rfr;
                bh[ni][0] = *(const unsigned*)&Bh[nn * KP + kb    ];
                bh[ni][1] = *(const unsigned*)&Bh[nn * KP + kb + 8];
                bl[ni][0] = *(const unsigned*)&Bl[nn * KP + kb    ];
                bl[ni][1] = *(const unsigned*)&Bl[nn * KP + kb + 8];
            }
            #pragma unroll
            for (int mi = 0; mi < MF; mi++)
                #pragma unroll
                for (int ni = 0; ni < NF; ni++) {
                    mma16816(acc[mi][ni], ah[mi], bh[ni]);
                    mma16816(acc[mi][ni], ah[mi], bl[ni]);
                    mma16816(acc[mi][ni], al[mi], bh[ni]);
                }
        }
        __syncthreads();
    }

    // epilogue
    #pragma unroll
    for (int mi = 0; mi < MF; mi++) {
        #pragma unroll
        for (int ni = 0; ni < NF; ni++) {
            int rr0 = row0 + wrow + mi * 16 + (lane >> 2);
            int cc0 = col0 + wcol + ni * 8 + (lane & 3) * 2;
            #pragma unroll
            for (int e = 0; e < 4; e++) {
                int rr = rr0 + ((e >= 2) ? 8 : 0);
                int cc = cc0 + (e & 1);
                if (rr < M && cc < N) {
                    float v = acc[mi][ni][e];
                    if (BIAS) v += bias[cc];
                    if (GELU) v = 0.5f * v * (1.0f + erff(v * 0.70710678118654752f));
                    size_t d = (size_t)rr * ldc + cc;
                    if (PLANES) {
                        fsplit(v, Ch[d], Cl[d]);
                    } else {
                        if (RES) v += res[d];
                        C[d] = v;
                    }
                }
            }
        }
    }
}

// ---------------- host launch ----------------
static inline int cdiv(int a, int b) { return (a + b - 1) / b; }
static inline int stage_bytes(int bm, int bn) { return 2 * ((bm + bn) * 80); }

extern "C" void kernel_launch(void* const* d_in, const int* in_sizes, int n_in,
                              void* d_out, int out_size) {
    const float* x      = (const float*)d_in[0];
    const float* W_emb  = (const float*)d_in[1];
    const float* b_emb  = (const float*)d_in[2];
    const float* ln1_g  = (const float*)d_in[3];
    const float* ln1_b  = (const float*)d_in[4];
    const float* W_qkv  = (const float*)d_in[5];
    const float* b_qkv  = (const float*)d_in[6];
    const float* W_proj = (const float*)d_in[7];
    const float* b_proj = (const float*)d_in[8];
    const float* ln2_g  = (const float*)d_in[9];
    const float* ln2_b  = (const float*)d_in[10];
    const float* W_mlp1 = (const float*)d_in[11];
    const float* b_mlp1 = (const float*)d_in[12];
    const float* W_mlp2 = (const float*)d_in[13];
    const float* b_mlp2 = (const float*)d_in[14];
    const float* lnf_g  = (const float*)d_in[15];
    const float* lnf_b  = (const float*)d_in[16];
    float* out = (float*)d_out;

    float *pH, *pQKV, *pS;
    BF *pLNh, *pLNl, *pQKh, *pQKl, *pOh, *pOl, *pMh, *pMl, *pPTh, *pPTl;
    BF *pPh, *pPl, *pVTh, *pVTl, *pWTh, *pWTl;
    cudaGetSymbolAddress((void**)&pH,   g_h);
    cudaGetSymbolAddress((void**)&pQKV, g_qkv);
    cudaGetSymbolAddress((void**)&pS,   g_S);
    cudaGetSymbolAddress((void**)&pLNh, g_ln_h);  cudaGetSymbolAddress((void**)&pLNl, g_ln_l);
    cudaGetSymbolAddress((void**)&pQKh, g_qk_h);  cudaGetSymbolAddress((void**)&pQKl, g_qk_l);
    cudaGetSymbolAddress((void**)&pOh,  g_o_h);   cudaGetSymbolAddress((void**)&pOl,  g_o_l);
    cudaGetSymbolAddress((void**)&pMh,  g_mlp_h); cudaGetSymbolAddress((void**)&pMl,  g_mlp_l);
    cudaGetSymbolAddress((void**)&pPTh, g_pt_h);  cudaGetSymbolAddress((void**)&pPTl, g_pt_l);
    cudaGetSymbolAddress((void**)&pPh,  g_p_h);   cudaGetSymbolAddress((void**)&pPl,  g_p_l);
    cudaGetSymbolAddress((void**)&pVTh, g_vt_h);  cudaGetSymbolAddress((void**)&pVTl, g_vt_l);
    cudaGetSymbolAddress((void**)&pWTh, g_wt_h);  cudaGetSymbolAddress((void**)&pWTl, g_wt_l);

    // instantiations
    auto G_BIAS   = gemm_bf<128,128,64,32, true, false,false,false>;   // +bias -> fp32
    auto G_PLAIN  = gemm_bf<128,128,64,32, false,false,false,false>;   // -> fp32 (S)
    auto G_PV     = gemm_bf<128, 64,64,32, false,false,false,true >;   // -> planes (O)
    auto G_BR     = gemm_bf<128,128,64,32, true, true, false,false>;   // +bias+res -> fp32
    auto G_GELU   = gemm_bf<128,128,64,32, true, false,true, true >;   // +bias+gelu -> planes

    int sm128 = 2 * stage_bytes(128, 128);   // 81920
    int sm64  = 2 * stage_bytes(128, 64);    // 61440
    cudaFuncSetAttribute(G_BIAS,  cudaFuncAttributeMaxDynamicSharedMemorySize, sm128);
    cudaFuncSetAttribute(G_PLAIN, cudaFuncAttributeMaxDynamicSharedMemorySize, sm128);
    cudaFuncSetAttribute(G_PV,    cudaFuncAttributeMaxDynamicSharedMemorySize, sm64);
    cudaFuncSetAttribute(G_BR,    cudaFuncAttributeMaxDynamicSharedMemorySize, sm128);
    cudaFuncSetAttribute(G_GELU,  cudaFuncAttributeMaxDynamicSharedMemorySize, sm128);

    dim3 tb(32, 8);

    // 0) weight transposes -> bf16 planes (once)
    transpose_kernel<<<dim3(cdiv(DIMV,32), cdiv(PINLEN,32)), tb>>>(W_emb, pWTh+OFF_EMB, pWTl+OFF_EMB, PINLEN, DIMV);
    for (int L = 0; L < 4; L++) {
        transpose_kernel<<<dim3(cdiv(3*DIMV,32), cdiv(DIMV,32)), tb>>>(
            W_qkv + (size_t)L*DIMV*3*DIMV, pWTh+OFF_QKV+(size_t)L*3*DIMV*DIMV, pWTl+OFF_QKV+(size_t)L*3*DIMV*DIMV, DIMV, 3*DIMV);
        transpose_kernel<<<dim3(cdiv(DIMV,32), cdiv(DIMV,32)), tb>>>(
            W_proj + (size_t)L*DIMV*DIMV, pWTh+OFF_PROJ+(size_t)L*DIMV*DIMV, pWTl+OFF_PROJ+(size_t)L*DIMV*DIMV, DIMV, DIMV);
        transpose_kernel<<<dim3(cdiv(HIDV,32), cdiv(DIMV,32)), tb>>>(
            W_mlp1 + (size_t)L*DIMV*HIDV, pWTh+OFF_MLP1+(size_t)L*DIMV*HIDV, pWTl+OFF_MLP1+(size_t)L*DIMV*HIDV, DIMV, HIDV);
        transpose_kernel<<<dim3(cdiv(DIMV,32), cdiv(HIDV,32)), tb>>>(
            W_mlp2 + (size_t)L*HIDV*DIMV, pWTh+OFF_MLP2+(size_t)L*HIDV*DIMV, pWTl+OFF_MLP2+(size_t)L*HIDV*DIMV, HIDV, DIMV);
    }

    // 1) patch gather -> planes
    patch_kernel<<<cdiv(MTOK * PINLEN, 256), 256>>>(x, pPTh, pPTl);

    // 2) embedding: [4092,112] @ W_emb^T + b -> h (fp32)
    G_BIAS<<<dim3(4, 32, 1), 256, sm128>>>(
        pPTh, pPTl, PINLEN, 0, 0, pWTh+OFF_EMB, pWTl+OFF_EMB, PINLEN, 0, 0,
        b_emb, nullptr, pH, nullptr, nullptr, DIMV, 0, 0, MTOK, DIMV, PINLEN, 1);

    cudaMemcpyAsync(out, pH, (size_t)MTOK * DIMV * sizeof(float),
                    cudaMemcpyDeviceToDevice, 0);

    const long long sQb = (long long)NPATCH * 3 * DIMV;
    const long long sSb = 8LL * NPATCH * SLD;
    const long long sSh = (long long)NPATCH * SLD;

    for (int L = 0; L < 4; L++) {
        ln_kernel<true><<<MTOK, 128>>>(pH, ln1_g + L*DIMV, ln1_b + L*DIMV, nullptr, pLNh, pLNl);

        // QKV -> fp32
        G_BIAS<<<dim3(12, 32, 1), 256, sm128>>>(
            pLNh, pLNl, DIMV, 0, 0,
            pWTh+OFF_QKV+(size_t)L*3*DIMV*DIMV, pWTl+OFF_QKV+(size_t)L*3*DIMV*DIMV, DIMV, 0, 0,
            b_qkv + L*3*DIMV, nullptr, pQKV, nullptr, nullptr, 3*DIMV, 0, 0, MTOK, 3*DIMV, DIMV, 1);

        // RoPE -> q,k planes;  V -> V^T planes
        rope_kernel<<<cdiv(MTOK * NHEAD * 32, 256), 256>>>(pQKV, pQKh, pQKl);
        vt_kernel<<<dim3(32, 2, 32), tb>>>(pQKV, pVTh, pVTl);

        // S = Q @ K^T (32 batch-heads), fp32 out ld=1024
        G_PLAIN<<<dim3(8, 8, 32), 256, sm128>>>(
            pQKh,        pQKl,        3*DIMV, sQb, HDIM,
            pQKh + DIMV, pQKl + DIMV, 3*DIMV, sQb, HDIM,
            nullptr, nullptr, pS, nullptr, nullptr, SLD, sSb, sSh,
            NPATCH, NPATCH, HDIM, NHEAD);

        softmax_kernel<<<32 * NPATCH, 256>>>(pS, pPh, pPl, NPATCH, 0.125f);

        // O = P @ V  (K padded to 1024, zero-filled) -> planes, head-concat layout
        G_PV<<<dim3(1, 8, 32), 128, sm64>>>(
            pPh, pPl, SLD, sSb, sSh,
            pVTh, pVTl, SLD, 8LL*HDIM*SLD, (long long)HDIM*SLD,
            nullptr, nullptr, nullptr, pOh, pOl, DIMV, (long long)NPATCH*DIMV, HDIM,
            NPATCH, HDIM, SLD, NHEAD);

        // proj + residual -> h (fp32)
        G_BR<<<dim3(4, 32, 1), 256, sm128>>>(
            pOh, pOl, DIMV, 0, 0,
            pWTh+OFF_PROJ+(size_t)L*DIMV*DIMV, pWTl+OFF_PROJ+(size_t)L*DIMV*DIMV, DIMV, 0, 0,
            b_proj + L*DIMV, pH, pH, nullptr, nullptr, DIMV, 0, 0, MTOK, DIMV, DIMV, 1);

        ln_kernel<true><<<MTOK, 128>>>(pH, ln2_g + L*DIMV, ln2_b + L*DIMV, nullptr, pLNh, pLNl);

        // MLP1 + bias + GELU -> planes
        G_GELU<<<dim3(16, 32, 1), 256, sm128>>>(
            pLNh, pLNl, DIMV, 0, 0,
            pWTh+OFF_MLP1+(size_t)L*DIMV*HIDV, pWTl+OFF_MLP1+(size_t)L*DIMV*HIDV, DIMV, 0, 0,
            b_mlp1 + L*HIDV, nullptr, nullptr, pMh, pMl, HIDV, 0, 0, MTOK, HIDV, DIMV, 1);

        // MLP2 + bias + residual -> h (fp32)
        G_BR<<<dim3(4, 32, 1), 256, sm128>>>(
            pMh, pMl, HIDV, 0, 0,
            pWTh+OFF_MLP2+(size_t)L*HIDV*DIMV, pWTl+OFF_MLP2+(size_t)L*HIDV*DIMV, HIDV, 0, 0,
            b_mlp2 + L*DIMV, pH, pH, nullptr, nullptr, DIMV, 0, 0, MTOK, DIMV, HIDV, 1);
    }

    // final LN -> fp32 d_out second half
    ln_kernel<false><<<MTOK, 128>>>(pH, lnf_g, lnf_b, out + (size_t)MTOK * DIMV, nullptr, nullptr);
}

// round 7
// speedup vs baseline: 3.6572x; 1.1054x over previous
#include <cuda_runtime.h>
#include <cuda_bf16.h>
#include <math.h>

typedef __nv_bfloat16 BF;

// ---------------- problem constants ----------------
#define BATCHN   4
#define SEQT     8192
#define NCH      7
#define NPATCH   1023               // (8192-16)/8+1
#define MTOK     (BATCHN*NPATCH)    // 4092
#define DIMV     512
#define HIDV     2048
#define NHEAD    8
#define HDIM     64
#define PINLEN   112                // PATCH_LEN*C = 16*7
#define SLD      1024               // padded key stride for V^T

// ---------------- device scratch (allocation-free) ----------------
__device__ __align__(256) float g_h    [MTOK*DIMV];       // residual stream fp32
__device__ __align__(256) float g_qkv  [MTOK*3*DIMV];     // fp32 qkv (pre-rope)
// bf16 hi/lo planes
__device__ __align__(256) BF g_ln_h [MTOK*DIMV],     g_ln_l [MTOK*DIMV];
__device__ __align__(256) BF g_qk_h [MTOK*3*DIMV],   g_qk_l [MTOK*3*DIMV];   // rope'd q,k planes
__device__ __align__(256) BF g_o_h  [MTOK*DIMV],     g_o_l  [MTOK*DIMV];
__device__ __align__(256) BF g_mlp_h[MTOK*HIDV],     g_mlp_l[MTOK*HIDV];
__device__ __align__(256) BF g_pt_h [MTOK*PINLEN],   g_pt_l [MTOK*PINLEN];
__device__ __align__(256) BF g_vt_h [32LL*HDIM*SLD], g_vt_l [32LL*HDIM*SLD];  // V^T planes
__device__ __align__(256) BF g_wt_h [12640256],      g_wt_l [12640256];       // transposed weights [N][K]

// weight-transpose scratch offsets (elements)
#define OFF_EMB   0
#define OFF_QKV   57344
#define OFF_PROJ  3203072
#define OFF_MLP1  4251648
#define OFF_MLP2  8445952

// ---------------- helpers ----------------
__device__ __forceinline__ void fsplit(float v, BF& h, BF& l) {
    h = __float2bfloat16_rn(v);
    l = __float2bfloat16_rn(v - __bfloat162float(h));
}
// split pair (a,b) into packed hi/lo bf16x2 words
__device__ __forceinline__ void split2(float a, float b, unsigned& hi, unsigned& lo) {
    union { unsigned u; BF h[2]; } uh, ul;
    fsplit(a, uh.h[0], ul.h[0]);
    fsplit(b, uh.h[1], ul.h[1]);
    hi = uh.u; lo = ul.u;
}
__device__ __forceinline__ unsigned cvta_s(const void* p) {
    return (unsigned)__cvta_generic_to_shared(p);
}
__device__ __forceinline__ void cp16(unsigned dst, const void* src, bool pred) {
    int sz = pred ? 16 : 0;
    asm volatile("cp.async.cg.shared.global [%0], [%1], 16, %2;\n"
                 :: "r"(dst), "l"(src), "r"(sz));
}
__device__ __forceinline__ void cp_commit() { asm volatile("cp.async.commit_group;\n"); }
__device__ __forceinline__ void cp_wait0()  { asm volatile("cp.async.wait_group 0;\n"); }

__device__ __forceinline__ void mma16816(float* d, const unsigned* a, const unsigned* b) {
    asm volatile(
        "mma.sync.aligned.m16n8k16.row.col.f32.bf16.bf16.f32 "
        "{%0,%1,%2,%3}, {%4,%5,%6,%7}, {%8,%9}, {%0,%1,%2,%3};"
        : "+f"(d[0]), "+f"(d[1]), "+f"(d[2]), "+f"(d[3])
        : "r"(a[0]), "r"(a[1]), "r"(a[2]), "r"(a[3]), "r"(b[0]), "r"(b[1]));
}

// ---------------- patch gather -> planes ----------------
__global__ void patch_kernel(const float* __restrict__ x, BF* __restrict__ oh, BF* __restrict__ ol) {
    int gid = blockIdx.x * blockDim.x + threadIdx.x;
    const int total = MTOK * PINLEN;
    if (gid >= total) return;
    int j = gid % PINLEN;
    int m = gid / PINLEN;
    int b = m / NPATCH;
    int p = m - b * NPATCH;
    int c = j >> 4;
    int t = j & 15;
    float v = x[((size_t)b * SEQT + (size_t)p * 8 + t) * NCH + c];
    fsplit(v, oh[gid], ol[gid]);
}

// ---------------- weight transpose -> planes: out[c][r] = in[r][c], in R x C ------
__global__ void transpose_kernel(const float* __restrict__ in, BF* __restrict__ oh,
                                 BF* __restrict__ ol, int R, int C) {
    __shared__ float t[32][33];
    int c0 = blockIdx.x * 32, r0 = blockIdx.y * 32;
    int tx = threadIdx.x, ty = threadIdx.y;   // 32 x 8
    #pragma unroll
    for (int i = 0; i < 32; i += 8) {
        int r = r0 + ty + i, c = c0 + tx;
        t[ty + i][tx] = (r < R && c < C) ? in[(size_t)r * C + c] : 0.f;
    }
    __syncthreads();
    #pragma unroll
    for (int i = 0; i < 32; i += 8) {
        int c = c0 + ty + i, r = r0 + tx;
        if (c < C && r < R) {
            size_t d = (size_t)c * R + r;
            fsplit(t[tx][ty + i], oh[d], ol[d]);
        }
    }
}

// ---------------- V^T planes: vt[z][d][p] = qkv[(b*NP+p)*1536 + 1024 + h*64 + d] ----
__global__ void vt_kernel(const float* __restrict__ qkv, BF* __restrict__ vh, BF* __restrict__ vl) {
    __shared__ float t[32][33];
    int z = blockIdx.z; int b = z >> 3, h = z & 7;
    int p0 = blockIdx.x * 32, d0 = blockIdx.y * 32;
    int tx = threadIdx.x, ty = threadIdx.y;
    const float* src = qkv + (size_t)b * NPATCH * (3 * DIMV) + 2 * DIMV + h * HDIM;
    #pragma unroll
    for (int i = 0; i < 32; i += 8) {
        int p = p0 + ty + i; int d = d0 + tx;
        t[ty + i][tx] = (p < NPATCH) ? src[(size_t)p * (3 * DIMV) + d] : 0.f;
    }
    __syncthreads();
    size_t zb = (size_t)z * HDIM * SLD;
    #pragma unroll
    for (int i = 0; i < 32; i += 8) {
        int d = d0 + ty + i, p = p0 + tx;
        size_t dst = zb + (size_t)d * SLD + p;           // p < 1024 always
        fsplit(t[tx][ty + i], vh[dst], vl[dst]);         // p==1023 -> 0 (zero pad)
    }
}

// ---------------- layernorm over 512: fp32 in; out planes OR fp32 ----------------
template<bool PLANES>
__global__ void ln_kernel(const float* __restrict__ in, const float* __restrict__ g,
                          const float* __restrict__ bb,
                          float* __restrict__ outf, BF* __restrict__ oh, BF* __restrict__ ol) {
    int row = blockIdx.x;
    int tid = threadIdx.x;                       // 128 threads, 1 float4 each
    const float4* xv = (const float4*)(in + (size_t)row * DIMV);
    float4 v = xv[tid];
    float s  = v.x + v.y + v.z + v.w;
    float s2 = v.x*v.x + v.y*v.y + v.z*v.z + v.w*v.w;
    #pragma unroll
    for (int o = 16; o > 0; o >>= 1) {
        s  += __shfl_xor_sync(0xFFFFFFFFu, s,  o);
        s2 += __shfl_xor_sync(0xFFFFFFFFu, s2, o);
    }
    __shared__ float sha[4], shb[4];
    int w = tid >> 5;
    if ((tid & 31) == 0) { sha[w] = s; shb[w] = s2; }
    __syncthreads();
    s  = sha[0] + sha[1] + sha[2] + sha[3];
    s2 = shb[0] + shb[1] + shb[2] + shb[3];
    float mu  = s * (1.0f / DIMV);
    float var = s2 * (1.0f / DIMV) - mu * mu;
    float rs  = rsqrtf(var + 1e-5f);
    float4 gg = ((const float4*)g)[tid];
    float4 bv = ((const float4*)bb)[tid];
    float o0 = (v.x - mu) * rs * gg.x + bv.x;
    float o1 = (v.y - mu) * rs * gg.y + bv.y;
    float o2 = (v.z - mu) * rs * gg.z + bv.z;
    float o3 = (v.w - mu) * rs * gg.w + bv.w;
    if (PLANES) {
        union { unsigned long long u; BF b[4]; } uh, ul;
        fsplit(o0, uh.b[0], ul.b[0]);
        fsplit(o1, uh.b[1], ul.b[1]);
        fsplit(o2, uh.b[2], ul.b[2]);
        fsplit(o3, uh.b[3], ul.b[3]);
        *(unsigned long long*)(oh + (size_t)row * DIMV + tid * 4) = uh.u;
        *(unsigned long long*)(ol + (size_t)row * DIMV + tid * 4) = ul.u;
    } else {
        float4 o = make_float4(o0, o1, o2, o3);
        ((float4*)(outf + (size_t)row * DIMV))[tid] = o;
    }
}

// ---------------- RoPE: read fp32 qkv, write rotated q,k planes ----------------
__global__ void rope_kernel(const float* __restrict__ qkv, BF* __restrict__ qh, BF* __restrict__ ql) {
    int gid = blockIdx.x * blockDim.x + threadIdx.x;
    const int total = MTOK * NHEAD * 32;
    if (gid >= total) return;
    int i = gid & 31;
    int h = (gid >> 5) & 7;
    int m = gid >> 8;
    int p = m % NPATCH;
    float inv = expf(-(float)i * 0.28782313662425574f);   // ln(10000)/32
    float ang = (float)p * inv;
    float sv, cv;
    sincosf(ang, &sv, &cv);
    size_t base = (size_t)m * (3 * DIMV) + h * HDIM;
    float q0 = qkv[base + i], q1 = qkv[base + 32 + i];
    fsplit(q0 * cv - q1 * sv, qh[base + i],      ql[base + i]);
    fsplit(q1 * cv + q0 * sv, qh[base + 32 + i], ql[base + 32 + i]);
    size_t kb = base + DIMV;
    float k0 = qkv[kb + i], k1 = qkv[kb + 32 + i];
    fsplit(k0 * cv - k1 * sv, qh[kb + i],      ql[kb + i]);
    fsplit(k1 * cv + k0 * sv, qh[kb + 32 + i], ql[kb + 32 + i]);
}

// ---------------- fused flash attention ----------------
// grid (8 q-tiles, 32 bh). CTA: 256 threads (8 warps x 16 q-rows).
// Q frags in regs; K tiles (128x64) and V^T tiles (64x128) double-buffered via cp.async.
__global__ void __launch_bounds__(256, 1)
flash_kernel(const BF* __restrict__ qkh, const BF* __restrict__ qkl,
             const BF* __restrict__ vth, const BF* __restrict__ vtl,
             BF* __restrict__ oh, BF* __restrict__ ol)
{
    constexpr int KPK = 72;                      // K tile row pitch (d elems)
    constexpr int KPV = 136;                     // V tile row pitch (key elems)
    constexpr int KB_ = 128 * KPK * 2;           // 18432 B per K plane
    constexpr int VB_ = 64  * KPV * 2;           // 17408 B per V plane
    constexpr int STG = 2 * KB_ + 2 * VB_;       // 71680 B per stage
    constexpr int NKT = 8;
    constexpr float SCALE = 0.125f;

    extern __shared__ char sm[];
    unsigned sb0 = cvta_s(sm);

    int z  = blockIdx.y; int bb = z >> 3, h = z & 7;
    int q0 = blockIdx.x * 128;
    int tid = threadIdx.x, wid = tid >> 5, lane = tid & 31;
    int rfr = lane >> 2, c2 = (lane & 3) * 2;
    int wrow = wid * 16;

    // ---- load Q fragments into registers (hi/lo), zero-fill invalid rows ----
    unsigned qa_h[4][4], qa_l[4][4];
    {
        int r0 = q0 + wrow + rfr, r1 = r0 + 8;
        bool ok0 = r0 < NPATCH, ok1 = r1 < NPATCH;
        size_t b0 = ((size_t)(bb * NPATCH + (ok0 ? r0 : 0))) * 1536 + h * 64;
        size_t b1 = ((size_t)(bb * NPATCH + (ok1 ? r1 : 0))) * 1536 + h * 64;
        #pragma unroll
        for (int kf = 0; kf < 4; kf++) {
            int kb = kf * 16 + c2;
            qa_h[kf][0] = ok0 ? *(const unsigned*)&qkh[b0 + kb]     : 0u;
            qa_h[kf][1] = ok1 ? *(const unsigned*)&qkh[b1 + kb]     : 0u;
            qa_h[kf][2] = ok0 ? *(const unsigned*)&qkh[b0 + kb + 8] : 0u;
            qa_h[kf][3] = ok1 ? *(const unsigned*)&qkh[b1 + kb + 8] : 0u;
            qa_l[kf][0] = ok0 ? *(const unsigned*)&qkl[b0 + kb]     : 0u;
            qa_l[kf][1] = ok1 ? *(const unsigned*)&qkl[b1 + kb]     : 0u;
            qa_l[kf][2] = ok0 ? *(const unsigned*)&qkl[b0 + kb + 8] : 0u;
            qa_l[kf][3] = ok1 ? *(const unsigned*)&qkl[b1 + kb + 8] : 0u;
        }
    }

    // ---- tile loaders (cp.async) ----
    auto issue = [&](int kt, int stage) {
        unsigned sb = sb0 + stage * STG;
        // K tile: 128 keys x 64 d, hi/lo. 2048 16B chunks / 256 thr = 8.
        #pragma unroll
        for (int i = 0; i < 8; i++) {
            int idx = tid + i * 256;
            bool pl = idx >= 1024;
            int id2 = idx & 1023;
            int r = id2 >> 3, ch = id2 & 7;
            int key = kt * 128 + r;
            bool ok = key < NPATCH;
            size_t src = ((size_t)(bb * NPATCH + (ok ? key : 0))) * 1536 + DIMV + h * 64 + ch * 8;
            cp16(sb + (pl ? KB_ : 0) + r * (KPK * 2) + ch * 16,
                 (pl ? qkl : qkh) + src, ok);
        }
        // V^T tile: 64 d x 128 keys, hi/lo (SLD-padded source: always valid).
        #pragma unroll
        for (int i = 0; i < 8; i++) {
            int idx = tid + i * 256;
            bool pl = idx >= 1024;
            int id2 = idx & 1023;
            int r = id2 >> 4, ch = id2 & 15;
            size_t src = (size_t)z * HDIM * SLD + (size_t)r * SLD + kt * 128 + ch * 8;
            cp16(sb + 2 * KB_ + (pl ? VB_ : 0) + r * (KPV * 2) + ch * 16,
                 (pl ? vtl : vth) + src, true);
        }
        cp_commit();
    };

    // ---- state ----
    float m0 = -1e30f, m1 = -1e30f, l0 = 0.f, l1 = 0.f;
    float accO[8][4];
    #pragma unroll
    for (int no = 0; no < 8; no++)
        #pragma unroll
        for (int e = 0; e < 4; e++) accO[no][e] = 0.f;

    issue(0, 0);

    for (int kt = 0; kt < NKT; kt++) {
        cp_wait0();
        __syncthreads();
        if (kt + 1 < NKT) issue(kt + 1, (kt + 1) & 1);

        const char* st = sm + (kt & 1) * STG;
        const BF* Kh = (const BF*)st;
        const BF* Kl = (const BF*)(st + KB_);
        const BF* Vh = (const BF*)(st + 2 * KB_);
        const BF* Vl = (const BF*)(st + 2 * KB_ + VB_);

        // ---- S = Q K^T (16 q-rows x 128 keys per warp) ----
        float acc[16][4];
        #pragma unroll
        for (int ni = 0; ni < 16; ni++) {
            acc[ni][0] = acc[ni][1] = acc[ni][2] = acc[ni][3] = 0.f;
            int nn = ni * 8 + rfr;
            #pragma unroll
            for (int kf = 0; kf < 4; kf++) {
                int kb = kf * 16 + c2;
                unsigned bh[2], bl[2];
                bh[0] = *(const unsigned*)&Kh[nn * KPK + kb];
                bh[1] = *(const unsigned*)&Kh[nn * KPK + kb + 8];
                bl[0] = *(const unsigned*)&Kl[nn * KPK + kb];
                bl[1] = *(const unsigned*)&Kl[nn * KPK + kb + 8];
                mma16816(acc[ni], qa_h[kf], bh);
                mma16816(acc[ni], qa_h[kf], bl);
                mma16816(acc[ni], qa_l[kf], bh);
            }
        }
        // mask padded key j==1023 (only last tile, local col 127 -> frag 15, odd col)
        if (kt == NKT - 1 && (lane & 3) == 3) {
            acc[15][1] = -1e30f;
            acc[15][3] = -1e30f;
        }
        // scale
        #pragma unroll
        for (int ni = 0; ni < 16; ni++) {
            acc[ni][0] *= SCALE; acc[ni][1] *= SCALE;
            acc[ni][2] *= SCALE; acc[ni][3] *= SCALE;
        }
        // ---- online softmax ----
        float tm0 = -1e30f, tm1 = -1e30f;
        #pragma unroll
        for (int ni = 0; ni < 16; ni++) {
            tm0 = fmaxf(tm0, fmaxf(acc[ni][0], acc[ni][1]));
            tm1 = fmaxf(tm1, fmaxf(acc[ni][2], acc[ni][3]));
        }
        tm0 = fmaxf(tm0, __shfl_xor_sync(0xFFFFFFFFu, tm0, 1));
        tm0 = fmaxf(tm0, __shfl_xor_sync(0xFFFFFFFFu, tm0, 2));
        tm1 = fmaxf(tm1, __shfl_xor_sync(0xFFFFFFFFu, tm1, 1));
        tm1 = fmaxf(tm1, __shfl_xor_sync(0xFFFFFFFFu, tm1, 2));
        float mn0 = fmaxf(m0, tm0), mn1 = fmaxf(m1, tm1);
        float al0 = __expf(m0 - mn0), al1 = __expf(m1 - mn1);
        m0 = mn0; m1 = mn1;
        float sum0 = 0.f, sum1 = 0.f;
        #pragma unroll
        for (int ni = 0; ni < 16; ni++) {
            acc[ni][0] = __expf(acc[ni][0] - mn0);
            acc[ni][1] = __expf(acc[ni][1] - mn0);
            acc[ni][2] = __expf(acc[ni][2] - mn1);
            acc[ni][3] = __expf(acc[ni][3] - mn1);
            sum0 += acc[ni][0] + acc[ni][1];
            sum1 += acc[ni][2] + acc[ni][3];
        }
        sum0 += __shfl_xor_sync(0xFFFFFFFFu, sum0, 1);
        sum0 += __shfl_xor_sync(0xFFFFFFFFu, sum0, 2);
        sum1 += __shfl_xor_sync(0xFFFFFFFFu, sum1, 1);
        sum1 += __shfl_xor_sync(0xFFFFFFFFu, sum1, 2);
        l0 = l0 * al0 + sum0;
        l1 = l1 * al1 + sum1;
        #pragma unroll
        for (int no = 0; no < 8; no++) {
            accO[no][0] *= al0; accO[no][1] *= al0;
            accO[no][2] *= al1; accO[no][3] *= al1;
        }
        // ---- O += P V : 8 k-chunks of 16 keys ----
        #pragma unroll
        for (int j = 0; j < 8; j++) {
            unsigned pah[4], pal[4];
            split2(acc[2*j][0],   acc[2*j][1],   pah[0], pal[0]);
            split2(acc[2*j][2],   acc[2*j][3],   pah[1], pal[1]);
            split2(acc[2*j+1][0], acc[2*j+1][1], pah[2], pal[2]);
            split2(acc[2*j+1][2], acc[2*j+1][3], pah[3], pal[3]);
            int kb = j * 16 + c2;
            #pragma unroll
            for (int no = 0; no < 8; no++) {
                int nn = no * 8 + rfr;
                unsigned vbh[2], vbl[2];
                vbh[0] = *(const unsigned*)&Vh[nn * KPV + kb];
                vbh[1] = *(const unsigned*)&Vh[nn * KPV + kb + 8];
                vbl[0] = *(const unsigned*)&Vl[nn * KPV + kb];
                vbl[1] = *(const unsigned*)&Vl[nn * KPV + kb + 8];
                mma16816(accO[no], pah, vbh);
                mma16816(accO[no], pah, vbl);
                mma16816(accO[no], pal, vbh);
            }
        }
        __syncthreads();
    }

    // ---- epilogue: O /= l, write planes in head-concat layout ----
    float il0 = 1.f / l0, il1 = 1.f / l1;
    int r0 = q0 + wrow + rfr, r1 = r0 + 8;
    #pragma unroll
    for (int no = 0; no < 8; no++) {
        int col = h * 64 + no * 8 + c2;
        if (r0 < NPATCH) {
            size_t d = ((size_t)(bb * NPATCH + r0)) * DIMV + col;
            fsplit(accO[no][0] * il0, oh[d],     ol[d]);
            fsplit(accO[no][1] * il0, oh[d + 1], ol[d + 1]);
        }
        if (r1 < NPATCH) {
            size_t d = ((size_t)(bb * NPATCH + r1)) * DIMV + col;
            fsplit(accO[no][2] * il1, oh[d],     ol[d]);
            fsplit(accO[no][3] * il1, oh[d + 1], ol[d + 1]);
        }
    }
}

// ---------------- bf16-plane tensor-core GEMM, cp.async 2-stage pipeline ----------
// C = A @ B^T. A: [M][K] planes (lda), B: [N][K] planes (ldb). 3-MMA hi/lo split.
template<int BM, int BN, int WM, int WN, bool BIAS, bool RES, bool GELU, bool PLANES>
__global__ void __launch_bounds__((BM/WM)*(BN/WN)*32)
gemm_bf(const BF* __restrict__ Ah_g, const BF* __restrict__ Al_g, int lda,
        const BF* __restrict__ Bh_g, const BF* __restrict__ Bl_g, int ldb,
        const float* __restrict__ bias, const float* __restrict__ res,
        float* __restrict__ C, BF* __restrict__ Ch, BF* __restrict__ Cl, int ldc,
        int M, int N, int K)
{
    constexpr int BK = 32, KP = 40;                 // 80-byte rows, conflict-free LDS
    constexpr int NWM = BM / WM, NWN = BN / WN;
    constexpr int THREADS = NWM * NWN * 32;
    constexpr int MF = WM / 16, NF = WN / 8;
    constexpr int CA = BM * (BK / 8) * 2;           // 16B chunks per stage (A, both planes)
    constexpr int CB = BN * (BK / 8) * 2;
    constexpr int TA = CA / THREADS, TB = CB / THREADS;
    constexpr int ROWB = KP * 2;                    // 80 bytes per row
    constexpr int OFF_AL_ = BM * ROWB;
    constexpr int OFF_BH_ = 2 * BM * ROWB;
    constexpr int OFF_BL_ = 2 * BM * ROWB + BN * ROWB;
    constexpr int STAGE = 2 * BM * ROWB + 2 * BN * ROWB;

    extern __shared__ char smraw[];

    int tid  = threadIdx.x;
    int row0 = blockIdx.y * BM;
    int col0 = blockIdx.x * BN;
    unsigned sbase0 = cvta_s(smraw);

    auto issue = [&](int kt, int stage) {
        int k0 = kt * BK;
        unsigned sb = sbase0 + stage * STAGE;
        #pragma unroll
        for (int i = 0; i < TA; i++) {
            int idx = tid + i * THREADS;
            bool lo = idx >= CA / 2;
            int id2 = lo ? idx - CA / 2 : idx;
            int r = id2 >> 2, ch = id2 & 3;
            int gk = k0 + ch * 8;
            int gr = row0 + r;
            bool ok = (gr < M) && (gk < K);
            int grc = ok ? gr : 0;
            const BF* src = (lo ? Al_g : Ah_g) + (size_t)grc * lda + (gk < K ? gk : 0);
            cp16(sb + (lo ? OFF_AL_ : 0) + r * ROWB + ch * 16, src, ok);
        }
        #pragma unroll
        for (int i = 0; i < TB; i++) {
            int idx = tid + i * THREADS;
            bool lo = idx >= CB / 2;
            int id2 = lo ? idx - CB / 2 : idx;
            int r = id2 >> 2, ch = id2 & 3;
            int gk = k0 + ch * 8;
            int gn = col0 + r;
            bool ok = (gn < N) && (gk < K);
            int gnc = ok ? gn : 0;
            const BF* src = (lo ? Bl_g : Bh_g) + (size_t)gnc * ldb + (gk < K ? gk : 0);
            cp16(sb + (lo ? OFF_BL_ : OFF_BH_) + r * ROWB + ch * 16, src, ok);
        }
        cp_commit();
    };

    int wid  = tid >> 5, lane = tid & 31;
    int wm   = wid % NWM, wn = wid / NWM;
    int wrow = wm * WM, wcol = wn * WN;
    int rfr  = lane >> 2, c2 = (lane & 3) * 2;

    float acc[MF][NF][4];
    #pragma unroll
    for (int mi = 0; mi < MF; mi++)
        #pragma unroll
        for (int ni = 0; ni < NF; ni++)
            #pragma unroll
            for (int e = 0; e < 4; e++) acc[mi][ni][e] = 0.f;

    int nk = (K + BK - 1) / BK;
    issue(0, 0);

    for (int kt = 0; kt < nk; kt++) {
        cp_wait0();
        __syncthreads();
        if (kt + 1 < nk) issue(kt + 1, (kt + 1) & 1);

        const char* st = smraw + (kt & 1) * STAGE;
        const BF* Ah = (const BF*)st;
        const BF* Al = (const BF*)(st + OFF_AL_);
        const BF* Bh = (const BF*)(st + OFF_BH_);
        const BF* Bl = (const BF*)(st + OFF_BL_);

        #pragma unroll
        for (int kk = 0; kk < 2; kk++) {
            int kb = kk * 16 + c2;
            unsigned ah[MF][4], al[MF][4], bh[NF][2], bl[NF][2];
            #pragma unroll
            for (int mi = 0; mi < MF; mi++) {
                int rr = wrow + mi * 16 + rfr;
                ah[mi][0] = *(const unsigned*)&Ah[(rr    ) * KP + kb    ];
                ah[mi][1] = *(const unsigned*)&Ah[(rr + 8) * KP + kb    ];
                ah[mi][2] = *(const unsigned*)&Ah[(rr    ) * KP + kb + 8];
                ah[mi][3] = *(const unsigned*)&Ah[(rr + 8) * KP + kb + 8];
                al[mi][0] = *(const unsigned*)&Al[(rr    ) * KP + kb    ];
                al[mi][1] = *(const unsigned*)&Al[(rr + 8) * KP + kb    ];
                al[mi][2] = *(const unsigned*)&Al[(rr    ) * KP + kb + 8];
                al[mi][3] = *(const unsigned*)&Al[(rr + 8) * KP + kb + 8];
            }
            #pragma unroll
            for (int ni = 0; ni < NF; ni++) {
                int nn = wcol + ni * 8 + rfr;
                bh[ni][0] = *(const unsigned*)&Bh[nn * KP + kb    ];
                bh[ni][1] = *(const unsigned*)&Bh[nn * KP + kb + 8];
                bl[ni][0] = *(const unsigned*)&Bl[nn * KP + kb    ];
                bl[ni][1] = *(const unsigned*)&Bl[nn * KP + kb + 8];
            }
            #pragma unroll
            for (int mi = 0; mi < MF; mi++)
                #pragma unroll
                for (int ni = 0; ni < NF; ni++) {
                    mma16816(acc[mi][ni], ah[mi], bh[ni]);
                    mma16816(acc[mi][ni], ah[mi], bl[ni]);
                    mma16816(acc[mi][ni], al[mi], bh[ni]);
                }
        }
        __syncthreads();
    }

    // epilogue
    #pragma unroll
    for (int mi = 0; mi < MF; mi++) {
        #pragma unroll
        for (int ni = 0; ni < NF; ni++) {
            int rr0 = row0 + wrow + mi * 16 + (lane >> 2);
            int cc0 = col0 + wcol + ni * 8 + (lane & 3) * 2;
            #pragma unroll
            for (int e = 0; e < 4; e++) {
                int rr = rr0 + ((e >= 2) ? 8 : 0);
                int cc = cc0 + (e & 1);
                if (rr < M && cc < N) {
                    float v = acc[mi][ni][e];
                    if (BIAS) v += bias[cc];
                    if (GELU) v = 0.5f * v * (1.0f + erff(v * 0.70710678118654752f));
                    size_t d = (size_t)rr * ldc + cc;
                    if (PLANES) {
                        fsplit(v, Ch[d], Cl[d]);
                    } else {
                        if (RES) v += res[d];
                        C[d] = v;
                    }
                }
            }
        }
    }
}

// ---------------- host launch ----------------
static inline int cdiv(int a, int b) { return (a + b - 1) / b; }

extern "C" void kernel_launch(void* const* d_in, const int* in_sizes, int n_in,
                              void* d_out, int out_size) {
    const float* x      = (const float*)d_in[0];
    const float* W_emb  = (const float*)d_in[1];
    const float* b_emb  = (const float*)d_in[2];
    const float* ln1_g  = (const float*)d_in[3];
    const float* ln1_b  = (const float*)d_in[4];
    const float* W_qkv  = (const float*)d_in[5];
    const float* b_qkv  = (const float*)d_in[6];
    const float* W_proj = (const float*)d_in[7];
    const float* b_proj = (const float*)d_in[8];
    const float* ln2_g  = (const float*)d_in[9];
    const float* ln2_b  = (const float*)d_in[10];
    const float* W_mlp1 = (const float*)d_in[11];
    const float* b_mlp1 = (const float*)d_in[12];
    const float* W_mlp2 = (const float*)d_in[13];
    const float* b_mlp2 = (const float*)d_in[14];
    const float* lnf_g  = (const float*)d_in[15];
    const float* lnf_b  = (const float*)d_in[16];
    float* out = (float*)d_out;

    float *pH, *pQKV;
    BF *pLNh, *pLNl, *pQKh, *pQKl, *pOh, *pOl, *pMh, *pMl, *pPTh, *pPTl;
    BF *pVTh, *pVTl, *pWTh, *pWTl;
    cudaGetSymbolAddress((void**)&pH,   g_h);
    cudaGetSymbolAddress((void**)&pQKV, g_qkv);
    cudaGetSymbolAddress((void**)&pLNh, g_ln_h);  cudaGetSymbolAddress((void**)&pLNl, g_ln_l);
    cudaGetSymbolAddress((void**)&pQKh, g_qk_h);  cudaGetSymbolAddress((void**)&pQKl, g_qk_l);
    cudaGetSymbolAddress((void**)&pOh,  g_o_h);   cudaGetSymbolAddress((void**)&pOl,  g_o_l);
    cudaGetSymbolAddress((void**)&pMh,  g_mlp_h); cudaGetSymbolAddress((void**)&pMl,  g_mlp_l);
    cudaGetSymbolAddress((void**)&pPTh, g_pt_h);  cudaGetSymbolAddress((void**)&pPTl, g_pt_l);
    cudaGetSymbolAddress((void**)&pVTh, g_vt_h);  cudaGetSymbolAddress((void**)&pVTl, g_vt_l);
    cudaGetSymbolAddress((void**)&pWTh, g_wt_h);  cudaGetSymbolAddress((void**)&pWTl, g_wt_l);

    // instantiations
    auto G_BIAS   = gemm_bf<128,128,64,32, true, false,false,false>;   // +bias -> fp32
    auto G_BR     = gemm_bf<128,128,64,32, true, true, false,false>;   // +bias+res -> fp32
    auto G_GELU   = gemm_bf<128,128,64,32, true, false,true, true >;   // +bias+gelu -> planes

    const int sm128 = 2 * 2 * (128 + 128) * 80;   // 81920
    cudaFuncSetAttribute(G_BIAS,  cudaFuncAttributeMaxDynamicSharedMemorySize, sm128);
    cudaFuncSetAttribute(G_BR,    cudaFuncAttributeMaxDynamicSharedMemorySize, sm128);
    cudaFuncSetAttribute(G_GELU,  cudaFuncAttributeMaxDynamicSharedMemorySize, sm128);
    const int smFlash = 2 * (2 * 128 * 72 * 2 + 2 * 64 * 136 * 2);     // 143360
    cudaFuncSetAttribute(flash_kernel, cudaFuncAttributeMaxDynamicSharedMemorySize, smFlash);

    dim3 tb(32, 8);

    // 0) weight transposes -> bf16 planes (once)
    transpose_kernel<<<dim3(cdiv(DIMV,32), cdiv(PINLEN,32)), tb>>>(W_emb, pWTh+OFF_EMB, pWTl+OFF_EMB, PINLEN, DIMV);
    for (int L = 0; L < 4; L++) {
        transpose_kernel<<<dim3(cdiv(3*DIMV,32), cdiv(DIMV,32)), tb>>>(
            W_qkv + (size_t)L*DIMV*3*DIMV, pWTh+OFF_QKV+(size_t)L*3*DIMV*DIMV, pWTl+OFF_QKV+(size_t)L*3*DIMV*DIMV, DIMV, 3*DIMV);
        transpose_kernel<<<dim3(cdiv(DIMV,32), cdiv(DIMV,32)), tb>>>(
            W_proj + (size_t)L*DIMV*DIMV, pWTh+OFF_PROJ+(size_t)L*DIMV*DIMV, pWTl+OFF_PROJ+(size_t)L*DIMV*DIMV, DIMV, DIMV);
        transpose_kernel<<<dim3(cdiv(HIDV,32), cdiv(DIMV,32)), tb>>>(
            W_mlp1 + (size_t)L*DIMV*HIDV, pWTh+OFF_MLP1+(size_t)L*DIMV*HIDV, pWTl+OFF_MLP1+(size_t)L*DIMV*HIDV, DIMV, HIDV);
        transpose_kernel<<<dim3(cdiv(DIMV,32), cdiv(HIDV,32)), tb>>>(
            W_mlp2 + (size_t)L*HIDV*DIMV, pWTh+OFF_MLP2+(size_t)L*HIDV*DIMV, pWTl+OFF_MLP2+(size_t)L*HIDV*DIMV, HIDV, DIMV);
    }

    // 1) patch gather -> planes
    patch_kernel<<<cdiv(MTOK * PINLEN, 256), 256>>>(x, pPTh, pPTl);

    // 2) embedding: [4092,112] @ W_emb^T + b -> h (fp32)
    G_BIAS<<<dim3(4, 32, 1), 256, sm128>>>(
        pPTh, pPTl, PINLEN, pWTh+OFF_EMB, pWTl+OFF_EMB, PINLEN,
        b_emb, nullptr, pH, nullptr, nullptr, DIMV, MTOK, DIMV, PINLEN);

    cudaMemcpyAsync(out, pH, (size_t)MTOK * DIMV * sizeof(float),
                    cudaMemcpyDeviceToDevice, 0);

    for (int L = 0; L < 4; L++) {
        ln_kernel<true><<<MTOK, 128>>>(pH, ln1_g + L*DIMV, ln1_b + L*DIMV, nullptr, pLNh, pLNl);

        // QKV -> fp32
        G_BIAS<<<dim3(12, 32, 1), 256, sm128>>>(
            pLNh, pLNl, DIMV,
            pWTh+OFF_QKV+(size_t)L*3*DIMV*DIMV, pWTl+OFF_QKV+(size_t)L*3*DIMV*DIMV, DIMV,
            b_qkv + L*3*DIMV, nullptr, pQKV, nullptr, nullptr, 3*DIMV, MTOK, 3*DIMV, DIMV);

        // RoPE -> q,k planes;  V -> V^T planes
        rope_kernel<<<cdiv(MTOK * NHEAD * 32, 256), 256>>>(pQKV, pQKh, pQKl);
        vt_kernel<<<dim3(32, 2, 32), tb>>>(pQKV, pVTh, pVTl);

        // fused attention -> O planes (head-concat layout)
        flash_kernel<<<dim3(8, 32), 256, smFlash>>>(pQKh, pQKl, pVTh, pVTl, pOh, pOl);

        // proj + residual -> h (fp32)
        G_BR<<<dim3(4, 32, 1), 256, sm128>>>(
            pOh, pOl, DIMV,
            pWTh+OFF_PROJ+(size_t)L*DIMV*DIMV, pWTl+OFF_PROJ+(size_t)L*DIMV*DIMV, DIMV,
            b_proj + L*DIMV, pH, pH, nullptr, nullptr, DIMV, MTOK, DIMV, DIMV);

        ln_kernel<true><<<MTOK, 128>>>(pH, ln2_g + L*DIMV, ln2_b + L*DIMV, nullptr, pLNh, pLNl);

        // MLP1 + bias + GELU -> planes
        G_GELU<<<dim3(16, 32, 1), 256, sm128>>>(
            pLNh, pLNl, DIMV,
            pWTh+OFF_MLP1+(size_t)L*DIMV*HIDV, pWTl+OFF_MLP1+(size_t)L*DIMV*HIDV, DIMV,
            b_mlp1 + L*HIDV, nullptr, nullptr, pMh, pMl, HIDV, MTOK, HIDV, DIMV);

        // MLP2 + bias + residual -> h (fp32)
        G_BR<<<dim3(4, 32, 1), 256, sm128>>>(
            pMh, pMl, HIDV,
            pWTh+OFF_MLP2+(size_t)L*HIDV*DIMV, pWTl+OFF_MLP2+(size_t)L*HIDV*DIMV, HIDV,
            b_mlp2 + L*DIMV, pH, pH, nullptr, nullptr, DIMV, MTOK, DIMV, HIDV);
    }

    // final LN -> fp32 d_out second half
    ln_kernel<false><<<MTOK, 128>>>(pH, lnf_g, lnf_b, out + (size_t)MTOK * DIMV, nullptr, nullptr);
}